// round 7
// baseline (speedup 1.0000x reference)
#include <cuda_runtime.h>
#include <cuda_bf16.h>
#include <cstdint>
#include <cstddef>
#include <math.h>

// ---------------------------------------------------------------------------
#define BB 2
#define HH 16
#define TT 2048
#define DD 2048
#define HD 128
#define KK 2048
#define MM 4096
#define SCALE 0.08838834764831845f
#define CH (BB * HH * TT * HD)

// ---------------------------------------------------------------------------
// Scratch (device globals; allocation is forbidden)
// ---------------------------------------------------------------------------
__device__ __nv_bfloat16 g_hs_h[MM * KK],  g_hs_l[MM * KK];
__device__ __nv_bfloat16 g_enc_h[MM * KK], g_enc_l[MM * KK];
__device__ __nv_bfloat16 g_wq_h[DD * KK], g_wq_l[DD * KK];
__device__ __nv_bfloat16 g_wk_h[DD * KK], g_wk_l[DD * KK];
__device__ __nv_bfloat16 g_wv_h[DD * KK], g_wv_l[DD * KK];
__device__ __nv_bfloat16 g_wo_h[DD * KK], g_wo_l[DD * KK];
__device__ __nv_bfloat16 g_q_h[CH], g_q_l[CH];     // [B,H,T,HD]
__device__ __nv_bfloat16 g_k_h[CH], g_k_l[CH];     // [B,H,S,HD]
__device__ __nv_bfloat16 g_v_h[CH], g_v_l[CH];     // [B,H,HD,S]  (transposed)
__device__ __nv_bfloat16 g_c_h[MM * DD], g_c_l[MM * DD];   // ctx [B,T,D]

// ---------------------------------------------------------------------------
// Helpers (baseline sm_80 features only)
// ---------------------------------------------------------------------------
__device__ __forceinline__ uint32_t smem_to_u32(const void* p) {
    uint32_t a;
    asm("{ .reg .u64 t; cvta.to.shared.u64 t, %1; cvt.u32.u64 %0, t; }" : "=r"(a) : "l"(p));
    return a;
}
__device__ __forceinline__ void cp_async16(uint32_t dst, const void* src) {
    asm volatile("cp.async.cg.shared.global [%0], [%1], 16;" :: "r"(dst), "l"(src));
}
#define CP_ASYNC_COMMIT() asm volatile("cp.async.commit_group;" ::: "memory")
#define CP_ASYNC_WAIT(n)  asm volatile("cp.async.wait_group %0;" :: "n"(n) : "memory")

__device__ __forceinline__ void ldm4(uint32_t* r, uint32_t addr) {
    asm volatile("ldmatrix.sync.aligned.m8n8.x4.shared.b16 {%0,%1,%2,%3}, [%4];"
                 : "=r"(r[0]), "=r"(r[1]), "=r"(r[2]), "=r"(r[3]) : "r"(addr));
}
__device__ __forceinline__ void mma16816(float* c, const uint32_t* a, uint32_t b0, uint32_t b1) {
    asm volatile("mma.sync.aligned.m16n8k16.row.col.f32.bf16.bf16.f32 "
                 "{%0,%1,%2,%3}, {%4,%5,%6,%7}, {%8,%9}, {%0,%1,%2,%3};"
                 : "+f"(c[0]), "+f"(c[1]), "+f"(c[2]), "+f"(c[3])
                 : "r"(a[0]), "r"(a[1]), "r"(a[2]), "r"(a[3]), "r"(b0), "r"(b1));
}
__device__ __forceinline__ uint32_t packbf(__nv_bfloat16 a, __nv_bfloat16 b) {
    __nv_bfloat162 t(a, b);
    return *reinterpret_cast<uint32_t*>(&t);
}
__device__ __forceinline__ void split_pack(float x, float y, uint32_t& hp, uint32_t& lp) {
    __nv_bfloat16 hx = __float2bfloat16(x), hy = __float2bfloat16(y);
    __nv_bfloat16 lx = __float2bfloat16(x - __bfloat162float(hx));
    __nv_bfloat16 ly = __float2bfloat16(y - __bfloat162float(hy));
    hp = packbf(hx, hy); lp = packbf(lx, ly);
}

// ---------------------------------------------------------------------------
// Fused fp32 -> bf16 hi/lo split for all 6 input tensors, MLP=4 per thread
// ---------------------------------------------------------------------------
#define NA4 ((size_t)MM * KK / 4)
#define NW4 ((size_t)DD * KK / 4)
#define SPLIT_TOT (2 * NA4 + 4 * NW4)

__global__ __launch_bounds__(256)
void split_all(const float* __restrict__ hs, const float* __restrict__ enc,
               const float* __restrict__ wq, const float* __restrict__ wk,
               const float* __restrict__ wv, const float* __restrict__ wo,
               __nv_bfloat16* __restrict__ hs_h, __nv_bfloat16* __restrict__ hs_l,
               __nv_bfloat16* __restrict__ enc_h, __nv_bfloat16* __restrict__ enc_l,
               __nv_bfloat16* __restrict__ wq_h, __nv_bfloat16* __restrict__ wq_l,
               __nv_bfloat16* __restrict__ wk_h, __nv_bfloat16* __restrict__ wk_l,
               __nv_bfloat16* __restrict__ wv_h, __nv_bfloat16* __restrict__ wv_l,
               __nv_bfloat16* __restrict__ wo_h, __nv_bfloat16* __restrict__ wo_l)
{
    size_t i = ((size_t)blockIdx.x * 256 + threadIdx.x) * 4;
    if (i >= SPLIT_TOT) return;
    const float* src; __nv_bfloat16 *hi, *lo; size_t base;
    if      (i < NA4)           { src = hs;  hi = hs_h;  lo = hs_l;  base = 0; }
    else if (i < 2 * NA4)       { src = enc; hi = enc_h; lo = enc_l; base = NA4; }
    else if (i < 2 * NA4 + NW4) { src = wq;  hi = wq_h;  lo = wq_l;  base = 2 * NA4; }
    else if (i < 2 * NA4 + 2 * NW4) { src = wk; hi = wk_h; lo = wk_l; base = 2 * NA4 + NW4; }
    else if (i < 2 * NA4 + 3 * NW4) { src = wv; hi = wv_h; lo = wv_l; base = 2 * NA4 + 2 * NW4; }
    else                        { src = wo;  hi = wo_h;  lo = wo_l;  base = 2 * NA4 + 3 * NW4; }
    const size_t j = i - base;
    float4 v[4];
    #pragma unroll
    for (int u = 0; u < 4; ++u) v[u] = ((const float4*)src)[j + u];
    #pragma unroll
    for (int u = 0; u < 4; ++u) {
        uint32_t h0, l0, h1, l1;
        split_pack(v[u].x, v[u].y, h0, l0);
        split_pack(v[u].z, v[u].w, h1, l1);
        ((uint32_t*)hi)[2 * (j + u)]     = h0;
        ((uint32_t*)hi)[2 * (j + u) + 1] = h1;
        ((uint32_t*)lo)[2 * (j + u)]     = l0;
        ((uint32_t*)lo)[2 * (j + u) + 1] = l1;
    }
}

// ---------------------------------------------------------------------------
// bf16x3 GEMM: 128x128 CTA tile, BK=32, **4 warps, warp tile 64x64** to cut
// smem crossbar traffic from 128B/HMMA to 85B/HMMA (round-6 finding:
// crossbar-bound, not occupancy-bound). 2-stage cp.async, 2 CTAs/SM.
// ---------------------------------------------------------------------------
#define TILE_B 10240
#define STAGE_B (4 * TILE_B)
#define SMEM_GEMM (2 * STAGE_B)        // 81920 -> 2 CTAs/SM
#define NSTAGES (KK / 32)
#define GTHREADS 128

__device__ __forceinline__ void load_stage_g(
    uint32_t sbuf, int s, int m0, int n0,
    const __nv_bfloat16* __restrict__ Ah, const __nv_bfloat16* __restrict__ Al,
    const __nv_bfloat16* __restrict__ Wh, const __nv_bfloat16* __restrict__ Wl, int tid)
{
    const int k0 = s * 32;
    #pragma unroll
    for (int q = 0; q < 4; ++q) {
        const int id = tid + GTHREADS * q;      // 0..511
        const int r = id >> 2, c = id & 3;
        const uint32_t doff = r * 80 + c * 16;
        const size_t gA = (size_t)(m0 + r) * KK + k0 + c * 8;
        const size_t gW = (size_t)(n0 + r) * KK + k0 + c * 8;
        cp_async16(sbuf + doff,              Ah + gA);
        cp_async16(sbuf + TILE_B + doff,     Al + gA);
        cp_async16(sbuf + 2 * TILE_B + doff, Wh + gW);
        cp_async16(sbuf + 3 * TILE_B + doff, Wl + gW);
    }
}

template<bool QKV>
__global__ __launch_bounds__(GTHREADS, 2)
void gemm_kernel(const __nv_bfloat16* __restrict__ a0h, const __nv_bfloat16* __restrict__ a0l,
                 const __nv_bfloat16* __restrict__ a1h, const __nv_bfloat16* __restrict__ a1l,
                 const __nv_bfloat16* __restrict__ wqh, const __nv_bfloat16* __restrict__ wql,
                 const __nv_bfloat16* __restrict__ wkh, const __nv_bfloat16* __restrict__ wkl,
                 const __nv_bfloat16* __restrict__ wvh, const __nv_bfloat16* __restrict__ wvl,
                 const float* __restrict__ cq, const float* __restrict__ sq,
                 const float* __restrict__ ck, const float* __restrict__ sk,
                 __nv_bfloat16* __restrict__ qh, __nv_bfloat16* __restrict__ ql,
                 __nv_bfloat16* __restrict__ kh, __nv_bfloat16* __restrict__ kl,
                 __nv_bfloat16* __restrict__ vh, __nv_bfloat16* __restrict__ vl,
                 float* __restrict__ fout)
{
    extern __shared__ __align__(128) uint8_t smem_raw[];
    const uint32_t sbase = smem_to_u32(smem_raw);
    const int tid = threadIdx.x;
    const int m0 = blockIdx.y * 128;
    const int n0 = blockIdx.x * 128;
    const int z  = QKV ? blockIdx.z : 0;

    const __nv_bfloat16 *Ah, *Al, *Wh, *Wl;
    if (QKV) {
        Ah = (z == 0) ? a0h : a1h;
        Al = (z == 0) ? a0l : a1l;
        Wh = (z == 0) ? wqh : (z == 1) ? wkh : wvh;
        Wl = (z == 0) ? wql : (z == 1) ? wkl : wvl;
    } else {
        Ah = a0h; Al = a0l; Wh = wqh; Wl = wql;
    }

    const int wid = tid >> 5, lid = tid & 31;
    const int wm = wid >> 1, wn = wid & 1;      // 2m x 2n warp grid
    const int g = lid >> 2, t = lid & 3;
    const int lrow = lid & 15;
    const int lcolb = (lid >> 4) * 16;

    // acc[mt 0..3][nt 0..7][4] : warp tile 64x64
    float acc[4][8][4];
    #pragma unroll
    for (int mt = 0; mt < 4; ++mt)
        #pragma unroll
        for (int nt = 0; nt < 8; ++nt)
            #pragma unroll
            for (int q = 0; q < 4; ++q) acc[mt][nt][q] = 0.0f;

    load_stage_g(sbase, 0, m0, n0, Ah, Al, Wh, Wl, tid);
    CP_ASYNC_COMMIT();

    for (int s = 0; s < NSTAGES; ++s) {
        if (s + 1 < NSTAGES) {
            load_stage_g(sbase + ((s + 1) & 1) * STAGE_B, s + 1, m0, n0, Ah, Al, Wh, Wl, tid);
            CP_ASYNC_COMMIT();
            CP_ASYNC_WAIT(1);
        } else {
            CP_ASYNC_WAIT(0);
        }
        __syncthreads();

        const uint32_t buf = sbase + (s & 1) * STAGE_B;
        const uint32_t aH = buf, aL = buf + TILE_B;
        const uint32_t bH = buf + 2 * TILE_B, bL = buf + 3 * TILE_B;

        #pragma unroll
        for (int kc = 0; kc < 2; ++kc) {
            const uint32_t cb = kc * 32 + lcolb;
            uint32_t ahf[4][4], alf[4][4], bf[4][4];
            #pragma unroll
            for (int mt = 0; mt < 4; ++mt) {
                const uint32_t ro = (wm * 64 + mt * 16 + lrow) * 80 + cb;
                ldm4(ahf[mt], aH + ro);
                ldm4(alf[mt], aL + ro);
            }
            #pragma unroll
            for (int jp = 0; jp < 4; ++jp)
                ldm4(bf[jp], bH + (wn * 64 + jp * 16 + lrow) * 80 + cb);
            // pass 1: Ah*Bh  (32 independent mma)
            #pragma unroll
            for (int jp = 0; jp < 4; ++jp)
                #pragma unroll
                for (int mt = 0; mt < 4; ++mt) {
                    mma16816(acc[mt][2 * jp],     ahf[mt], bf[jp][0], bf[jp][2]);
                    mma16816(acc[mt][2 * jp + 1], ahf[mt], bf[jp][1], bf[jp][3]);
                }
            // pass 2: Al*Bh
            #pragma unroll
            for (int jp = 0; jp < 4; ++jp)
                #pragma unroll
                for (int mt = 0; mt < 4; ++mt) {
                    mma16816(acc[mt][2 * jp],     alf[mt], bf[jp][0], bf[jp][2]);
                    mma16816(acc[mt][2 * jp + 1], alf[mt], bf[jp][1], bf[jp][3]);
                }
            // reload B-lo, pass 3: Ah*Bl
            #pragma unroll
            for (int jp = 0; jp < 4; ++jp)
                ldm4(bf[jp], bL + (wn * 64 + jp * 16 + lrow) * 80 + cb);
            #pragma unroll
            for (int jp = 0; jp < 4; ++jp)
                #pragma unroll
                for (int mt = 0; mt < 4; ++mt) {
                    mma16816(acc[mt][2 * jp],     ahf[mt], bf[jp][0], bf[jp][2]);
                    mma16816(acc[mt][2 * jp + 1], ahf[mt], bf[jp][1], bf[jp][3]);
                }
        }
        __syncthreads();
    }

    // ---------------- epilogue ----------------
    #pragma unroll
    for (int mt = 0; mt < 4; ++mt) {
        #pragma unroll
        for (int rh = 0; rh < 2; ++rh) {
            const int m = m0 + wm * 64 + mt * 16 + g + rh * 8;
            const int tI = m & (TT - 1);
            const int b  = m >> 11;
            #pragma unroll
            for (int nt = 0; nt < 8; ++nt) {
                const int col = wn * 64 + nt * 8 + 2 * t;
                float v0 = acc[mt][nt][rh * 2 + 0];
                float v1 = acc[mt][nt][rh * 2 + 1];
                if (QKV) {
                    if (z < 2) {
                        const float* cT = (z == 0) ? cq : ck;
                        const float* sT = (z == 0) ? sq : sk;
                        const int d2 = col >> 1;
                        const float cs = cT[tI * 64 + d2];
                        const float sn = sT[tI * 64 + d2];
                        const float x0 = v0, x1 = v1;
                        v0 = x0 * cs - x1 * sn;
                        v1 = x1 * cs + x0 * sn;
                    }
                    const int hhead = blockIdx.x;
                    const size_t bh = (size_t)b * HH + hhead;
                    __nv_bfloat16 h0 = __float2bfloat16(v0), h1 = __float2bfloat16(v1);
                    __nv_bfloat16 e0 = __float2bfloat16(v0 - __bfloat162float(h0));
                    __nv_bfloat16 e1 = __float2bfloat16(v1 - __bfloat162float(h1));
                    if (z == 2) {
                        const size_t base = (bh * HD + col) * TT + tI;
                        vh[base] = h0; vh[base + TT] = h1;
                        vl[base] = e0; vl[base + TT] = e1;
                    } else {
                        const size_t off = (bh * TT + tI) * HD + col;
                        __nv_bfloat16* oh = (z == 0) ? qh : kh;
                        __nv_bfloat16* ol = (z == 0) ? ql : kl;
                        *(uint32_t*)(oh + off) = packbf(h0, h1);
                        *(uint32_t*)(ol + off) = packbf(e0, e1);
                    }
                } else {
                    float* op = fout + (size_t)m * DD + n0 + col;
                    *(float2*)op = make_float2(v0, v1);
                }
            }
        }
    }
}

// ---------------------------------------------------------------------------
// Flash attention, mma.sync bf16x3, pass-reordered (unchanged this round)
// ---------------------------------------------------------------------------
#define AQ_STR 272
#define AV_STR 144
#define OFF_QL 34816
#define OFF_KV 69632
#define KV_BUF 71680
#define OFF_KL 17408
#define OFF_VH 34816
#define OFF_VL 53248
#define ATT_SMEM (OFF_KV + 2 * KV_BUF)

__device__ __forceinline__ void load_kv_chunk(
    uint32_t sb, int buf, int chunk, int bh,
    const __nv_bfloat16* __restrict__ kh_g, const __nv_bfloat16* __restrict__ kl_g,
    const __nv_bfloat16* __restrict__ vh_g, const __nv_bfloat16* __restrict__ vl_g, int tid)
{
    const uint32_t kb = sb + OFF_KV + buf * KV_BUF;
    const int s0 = chunk * 64;
    #pragma unroll
    for (int i = 0; i < 4; ++i) {
        const int idx = tid + 256 * i;
        const int r = idx >> 4, c2 = idx & 15;
        const size_t gk = ((size_t)bh * TT + s0 + r) * HD + c2 * 8;
        cp_async16(kb + r * AQ_STR + c2 * 16,          kh_g + gk);
        cp_async16(kb + OFF_KL + r * AQ_STR + c2 * 16, kl_g + gk);
        const int rv = idx >> 3, cv = idx & 7;
        const size_t gv = ((size_t)bh * HD + rv) * TT + s0 + cv * 8;
        cp_async16(kb + OFF_VH + rv * AV_STR + cv * 16, vh_g + gv);
        cp_async16(kb + OFF_VL + rv * AV_STR + cv * 16, vl_g + gv);
    }
}

__global__ __launch_bounds__(256, 1)
void attn_kernel(const __nv_bfloat16* __restrict__ qh_g, const __nv_bfloat16* __restrict__ ql_g,
                 const __nv_bfloat16* __restrict__ kh_g, const __nv_bfloat16* __restrict__ kl_g,
                 const __nv_bfloat16* __restrict__ vh_g, const __nv_bfloat16* __restrict__ vl_g,
                 __nv_bfloat16* __restrict__ ch_g, __nv_bfloat16* __restrict__ cl_g)
{
    extern __shared__ __align__(128) uint8_t sm_raw[];
    const uint32_t sb = smem_to_u32(sm_raw);
    const int tid = threadIdx.x;
    const int wid = tid >> 5, lid = tid & 31;
    const int g = lid >> 2, t = lid & 3;
    const int bh = blockIdx.y;
    const int b = bh >> 4, h = bh & 15;
    const int q0 = blockIdx.x * 128;
    const int lrow = lid & 15;
    const int lcolb = (lid >> 4) * 16;

    const size_t qoff = ((size_t)bh * TT + q0) * HD;
    #pragma unroll
    for (int i = 0; i < 8; ++i) {
        const int idx = tid + 256 * i;
        const int r = idx >> 4, c2 = idx & 15;
        const size_t gq = qoff + (size_t)r * HD + c2 * 8;
        cp_async16(sb + r * AQ_STR + c2 * 16,          qh_g + gq);
        cp_async16(sb + OFF_QL + r * AQ_STR + c2 * 16, ql_g + gq);
    }
    load_kv_chunk(sb, 0, 0, bh, kh_g, kl_g, vh_g, vl_g, tid);
    CP_ASYNC_COMMIT();
    load_kv_chunk(sb, 1, 1, bh, kh_g, kl_g, vh_g, vl_g, tid);
    CP_ASYNC_COMMIT();

    float O[16][4];
    #pragma unroll
    for (int nv = 0; nv < 16; ++nv)
        #pragma unroll
        for (int q = 0; q < 4; ++q) O[nv][q] = 0.0f;
    float mr0 = -1e30f, mr1 = -1e30f, lr0 = 0.0f, lr1 = 0.0f;

    for (int c = 0; c < 32; ++c) {
        CP_ASYNC_WAIT(1);
        __syncthreads();
        const uint32_t kb = sb + OFF_KV + (c & 1) * KV_BUF;

        // ---- S = Q K^T (bf16x3, pass-reordered) ----
        float S[8][4];
        #pragma unroll
        for (int j = 0; j < 8; ++j)
            #pragma unroll
            for (int q = 0; q < 4; ++q) S[j][q] = 0.0f;

        #pragma unroll
        for (int ks = 0; ks < 8; ++ks) {
            const uint32_t cb = ks * 32 + lcolb;
            uint32_t qhf[4], qlf[4], kf[4][4];
            const uint32_t qo = (wid * 16 + lrow) * AQ_STR + cb;
            ldm4(qhf, sb + qo);
            ldm4(qlf, sb + OFF_QL + qo);
            #pragma unroll
            for (int jp = 0; jp < 4; ++jp)
                ldm4(kf[jp], kb + (jp * 16 + lrow) * AQ_STR + cb);
            #pragma unroll
            for (int jp = 0; jp < 4; ++jp) {
                mma16816(S[2 * jp],     qhf, kf[jp][0], kf[jp][2]);
                mma16816(S[2 * jp + 1], qhf, kf[jp][1], kf[jp][3]);
            }
            #pragma unroll
            for (int jp = 0; jp < 4; ++jp) {
                mma16816(S[2 * jp],     qlf, kf[jp][0], kf[jp][2]);
                mma16816(S[2 * jp + 1], qlf, kf[jp][1], kf[jp][3]);
            }
            #pragma unroll
            for (int jp = 0; jp < 4; ++jp)
                ldm4(kf[jp], kb + OFF_KL + (jp * 16 + lrow) * AQ_STR + cb);
            #pragma unroll
            for (int jp = 0; jp < 4; ++jp) {
                mma16816(S[2 * jp],     qhf, kf[jp][0], kf[jp][2]);
                mma16816(S[2 * jp + 1], qhf, kf[jp][1], kf[jp][3]);
            }
        }

        // ---- online softmax ----
        float mx0 = -1e30f, mx1 = -1e30f;
        #pragma unroll
        for (int j = 0; j < 8; ++j) {
            #pragma unroll
            for (int q = 0; q < 4; ++q) S[j][q] *= SCALE;
            mx0 = fmaxf(mx0, fmaxf(S[j][0], S[j][1]));
            mx1 = fmaxf(mx1, fmaxf(S[j][2], S[j][3]));
        }
        mx0 = fmaxf(mx0, __shfl_xor_sync(0xffffffffu, mx0, 1));
        mx0 = fmaxf(mx0, __shfl_xor_sync(0xffffffffu, mx0, 2));
        mx1 = fmaxf(mx1, __shfl_xor_sync(0xffffffffu, mx1, 1));
        mx1 = fmaxf(mx1, __shfl_xor_sync(0xffffffffu, mx1, 2));
        const float mn0 = fmaxf(mr0, mx0), mn1 = fmaxf(mr1, mx1);
        const float cr0 = __expf(mr0 - mn0), cr1 = __expf(mr1 - mn1);
        mr0 = mn0; mr1 = mn1;
        float ls0 = 0.0f, ls1 = 0.0f;
        #pragma unroll
        for (int j = 0; j < 8; ++j) {
            S[j][0] = __expf(S[j][0] - mn0);
            S[j][1] = __expf(S[j][1] - mn0);
            S[j][2] = __expf(S[j][2] - mn1);
            S[j][3] = __expf(S[j][3] - mn1);
            ls0 += S[j][0] + S[j][1];
            ls1 += S[j][2] + S[j][3];
        }
        ls0 += __shfl_xor_sync(0xffffffffu, ls0, 1);
        ls0 += __shfl_xor_sync(0xffffffffu, ls0, 2);
        ls1 += __shfl_xor_sync(0xffffffffu, ls1, 1);
        ls1 += __shfl_xor_sync(0xffffffffu, ls1, 2);
        lr0 = lr0 * cr0 + ls0;
        lr1 = lr1 * cr1 + ls1;
        #pragma unroll
        for (int nv = 0; nv < 16; ++nv) {
            O[nv][0] *= cr0; O[nv][1] *= cr0;
            O[nv][2] *= cr1; O[nv][3] *= cr1;
        }

        // ---- P fragments ----
        uint32_t ph[4][4], pl[4][4];
        #pragma unroll
        for (int kk = 0; kk < 4; ++kk) {
            split_pack(S[2 * kk][0],     S[2 * kk][1],     ph[kk][0], pl[kk][0]);
            split_pack(S[2 * kk][2],     S[2 * kk][3],     ph[kk][1], pl[kk][1]);
            split_pack(S[2 * kk + 1][0], S[2 * kk + 1][1], ph[kk][2], pl[kk][2]);
            split_pack(S[2 * kk + 1][2], S[2 * kk + 1][3], ph[kk][3], pl[kk][3]);
        }

        // ---- O += P V (bf16x3, pass-reordered over np-halves) ----
        const uint32_t vbh = kb + OFF_VH, vbl = kb + OFF_VL;
        #pragma unroll
        for (int kk = 0; kk < 4; ++kk) {
            const uint32_t cb = kk * 32 + lcolb;
            #pragma unroll
            for (int half = 0; half < 2; ++half) {
                uint32_t vf[4][4];
                #pragma unroll
                for (int u = 0; u < 4; ++u)
                    ldm4(vf[u], vbh + ((half * 4 + u) * 16 + lrow) * AV_STR + cb);
                #pragma unroll
                for (int u = 0; u < 4; ++u) {
                    const int np = half * 4 + u;
                    mma16816(O[2 * np],     ph[kk], vf[u][0], vf[u][2]);
                    mma16816(O[2 * np + 1], ph[kk], vf[u][1], vf[u][3]);
                }
                #pragma unroll
                for (int u = 0; u < 4; ++u) {
                    const int np = half * 4 + u;
                    mma16816(O[2 * np],     pl[kk], vf[u][0], vf[u][2]);
                    mma16816(O[2 * np + 1], pl[kk], vf[u][1], vf[u][3]);
                }
                #pragma unroll
                for (int u = 0; u < 4; ++u)
                    ldm4(vf[u], vbl + ((half * 4 + u) * 16 + lrow) * AV_STR + cb);
                #pragma unroll
                for (int u = 0; u < 4; ++u) {
                    const int np = half * 4 + u;
                    mma16816(O[2 * np],     ph[kk], vf[u][0], vf[u][2]);
                    mma16816(O[2 * np + 1], ph[kk], vf[u][1], vf[u][3]);
                }
            }
        }

        __syncthreads();
        if (c + 2 < 32)
            load_kv_chunk(sb, c & 1, c + 2, bh, kh_g, kl_g, vh_g, vl_g, tid);
        CP_ASYNC_COMMIT();
    }

    // ---- epilogue ----
    const float inv0 = 1.0f / lr0, inv1 = 1.0f / lr1;
    const int t0 = q0 + wid * 16 + g;
    const int t1 = t0 + 8;
    #pragma unroll
    for (int nv = 0; nv < 16; ++nv) {
        const int d = h * HD + nv * 8 + 2 * t;
        const size_t o0 = ((size_t)b * TT + t0) * DD + d;
        const size_t o1 = ((size_t)b * TT + t1) * DD + d;
        uint32_t hp, lp;
        split_pack(O[nv][0] * inv0, O[nv][1] * inv0, hp, lp);
        *(uint32_t*)(ch_g + o0) = hp;
        *(uint32_t*)(cl_g + o0) = lp;
        split_pack(O[nv][2] * inv1, O[nv][3] * inv1, hp, lp);
        *(uint32_t*)(ch_g + o1) = hp;
        *(uint32_t*)(cl_g + o1) = lp;
    }
}

// ---------------------------------------------------------------------------
extern "C" void kernel_launch(void* const* d_in, const int* in_sizes, int n_in,
                              void* d_out, int out_size)
{
    const float* hs  = (const float*)d_in[0];
    const float* enc = (const float*)d_in[1];
    const float* Wq  = (const float*)d_in[2];
    const float* Wk  = (const float*)d_in[3];
    const float* Wv  = (const float*)d_in[4];
    const float* Wo  = (const float*)d_in[5];
    const float* cq  = (const float*)d_in[6];
    const float* sq  = (const float*)d_in[7];
    const float* ck  = (const float*)d_in[8];
    const float* sk  = (const float*)d_in[9];

    __nv_bfloat16 *hs_h, *hs_l, *enc_h, *enc_l;
    __nv_bfloat16 *wq_h, *wq_l, *wk_h, *wk_l, *wv_h, *wv_l, *wo_h, *wo_l;
    __nv_bfloat16 *q_h, *q_l, *k_h, *k_l, *v_h, *v_l, *c_h, *c_l;
    cudaGetSymbolAddress((void**)&hs_h,  g_hs_h);  cudaGetSymbolAddress((void**)&hs_l,  g_hs_l);
    cudaGetSymbolAddress((void**)&enc_h, g_enc_h); cudaGetSymbolAddress((void**)&enc_l, g_enc_l);
    cudaGetSymbolAddress((void**)&wq_h,  g_wq_h);  cudaGetSymbolAddress((void**)&wq_l,  g_wq_l);
    cudaGetSymbolAddress((void**)&wk_h,  g_wk_h);  cudaGetSymbolAddress((void**)&wk_l,  g_wk_l);
    cudaGetSymbolAddress((void**)&wv_h,  g_wv_h);  cudaGetSymbolAddress((void**)&wv_l,  g_wv_l);
    cudaGetSymbolAddress((void**)&wo_h,  g_wo_h);  cudaGetSymbolAddress((void**)&wo_l,  g_wo_l);
    cudaGetSymbolAddress((void**)&q_h, g_q_h); cudaGetSymbolAddress((void**)&q_l, g_q_l);
    cudaGetSymbolAddress((void**)&k_h, g_k_h); cudaGetSymbolAddress((void**)&k_l, g_k_l);
    cudaGetSymbolAddress((void**)&v_h, g_v_h); cudaGetSymbolAddress((void**)&v_l, g_v_l);
    cudaGetSymbolAddress((void**)&c_h, g_c_h); cudaGetSymbolAddress((void**)&c_l, g_c_l);

    {
        const size_t nthreads = SPLIT_TOT / 4;
        split_all<<<(unsigned)((nthreads + 255) / 256), 256>>>(
            hs, enc, Wq, Wk, Wv, Wo,
            hs_h, hs_l, enc_h, enc_l, wq_h, wq_l, wk_h, wk_l, wv_h, wv_l, wo_h, wo_l);
    }

    cudaFuncSetAttribute(gemm_kernel<true>,
                         cudaFuncAttributeMaxDynamicSharedMemorySize, SMEM_GEMM);
    cudaFuncSetAttribute(gemm_kernel<false>,
                         cudaFuncAttributeMaxDynamicSharedMemorySize, SMEM_GEMM);
    cudaFuncSetAttribute(attn_kernel,
                         cudaFuncAttributeMaxDynamicSharedMemorySize, ATT_SMEM);

    // Q/K/V projections (+RoPE, +head split, +V transpose, bf16 h/l outputs)
    gemm_kernel<true><<<dim3(DD / 128, MM / 128, 3), GTHREADS, SMEM_GEMM>>>(
        hs_h, hs_l, enc_h, enc_l, wq_h, wq_l, wk_h, wk_l, wv_h, wv_l,
        cq, sq, ck, sk, q_h, q_l, k_h, k_l, v_h, v_l, nullptr);

    // Attention
    attn_kernel<<<dim3(TT / 128, BB * HH), 256, ATT_SMEM>>>(
        q_h, q_l, k_h, k_l, v_h, v_l, c_h, c_l);

    // Output projection (fp32 out)
    gemm_kernel<false><<<dim3(DD / 128, MM / 128, 1), GTHREADS, SMEM_GEMM>>>(
        c_h, c_l, nullptr, nullptr, wo_h, wo_l, nullptr, nullptr, nullptr, nullptr,
        nullptr, nullptr, nullptr, nullptr,
        nullptr, nullptr, nullptr, nullptr, nullptr, nullptr, (float*)d_out);
}

// round 8
// speedup vs baseline: 1.1264x; 1.1264x over previous
#include <cuda_runtime.h>
#include <cuda_fp16.h>
#include <cstdint>
#include <cstddef>
#include <math.h>

// ---------------------------------------------------------------------------
#define BB 2
#define HH 16
#define TT 2048
#define DD 2048
#define HD 128
#define KK 2048
#define MM 4096
#define SCALE 0.08838834764831845f
#define CH (BB * HH * TT * HD)

// ---------------------------------------------------------------------------
// Scratch (device globals; allocation is forbidden).  All fp16 hi/lo pairs.
// ---------------------------------------------------------------------------
__device__ __half g_hs_h[MM * KK],  g_hs_l[MM * KK];
__device__ __half g_enc_h[MM * KK], g_enc_l[MM * KK];
__device__ __half g_wq_h[DD * KK], g_wq_l[DD * KK];
__device__ __half g_wk_h[DD * KK], g_wk_l[DD * KK];
__device__ __half g_wv_h[DD * KK], g_wv_l[DD * KK];
__device__ __half g_wo_h[DD * KK], g_wo_l[DD * KK];
__device__ __half g_q_h[CH], g_q_l[CH];     // [B,H,T,HD]
__device__ __half g_k_h[CH], g_k_l[CH];     // [B,H,S,HD]
__device__ __half g_v_h[CH];                // [B,H,HD,S] transposed, SINGLE fp16
__device__ __half g_c_h[MM * DD], g_c_l[MM * DD];   // ctx [B,T,D]

// ---------------------------------------------------------------------------
// Helpers (baseline sm_80 features only)
// ---------------------------------------------------------------------------
__device__ __forceinline__ uint32_t smem_to_u32(const void* p) {
    uint32_t a;
    asm("{ .reg .u64 t; cvta.to.shared.u64 t, %1; cvt.u32.u64 %0, t; }" : "=r"(a) : "l"(p));
    return a;
}
__device__ __forceinline__ void cp_async16(uint32_t dst, const void* src) {
    asm volatile("cp.async.cg.shared.global [%0], [%1], 16;" :: "r"(dst), "l"(src));
}
#define CP_ASYNC_COMMIT() asm volatile("cp.async.commit_group;" ::: "memory")
#define CP_ASYNC_WAIT(n)  asm volatile("cp.async.wait_group %0;" :: "n"(n) : "memory")

__device__ __forceinline__ void ldm4(uint32_t* r, uint32_t addr) {
    asm volatile("ldmatrix.sync.aligned.m8n8.x4.shared.b16 {%0,%1,%2,%3}, [%4];"
                 : "=r"(r[0]), "=r"(r[1]), "=r"(r[2]), "=r"(r[3]) : "r"(addr));
}
// fp16 inputs, fp32 accumulate
__device__ __forceinline__ void mma16816(float* c, const uint32_t* a, uint32_t b0, uint32_t b1) {
    asm volatile("mma.sync.aligned.m16n8k16.row.col.f32.f16.f16.f32 "
                 "{%0,%1,%2,%3}, {%4,%5,%6,%7}, {%8,%9}, {%0,%1,%2,%3};"
                 : "+f"(c[0]), "+f"(c[1]), "+f"(c[2]), "+f"(c[3])
                 : "r"(a[0]), "r"(a[1]), "r"(a[2]), "r"(a[3]), "r"(b0), "r"(b1));
}
__device__ __forceinline__ uint32_t packhf(__half a, __half b) {
    __half2 t(a, b);
    return *reinterpret_cast<uint32_t*>(&t);
}
__device__ __forceinline__ void split_pack(float x, float y, uint32_t& hp, uint32_t& lp) {
    __half hx = __float2half(x), hy = __float2half(y);
    __half lx = __float2half(x - __half2float(hx));
    __half ly = __float2half(y - __half2float(hy));
    hp = packhf(hx, hy); lp = packhf(lx, ly);
}

// ---------------------------------------------------------------------------
// Fused fp32 -> fp16 hi/lo split for all 6 input tensors
// ---------------------------------------------------------------------------
#define NA4 ((size_t)MM * KK / 4)
#define NW4 ((size_t)DD * KK / 4)
#define SPLIT_TOT (2 * NA4 + 4 * NW4)

__global__ __launch_bounds__(256)
void split_all(const float* __restrict__ hs, const float* __restrict__ enc,
               const float* __restrict__ wq, const float* __restrict__ wk,
               const float* __restrict__ wv, const float* __restrict__ wo,
               __half* __restrict__ hs_h, __half* __restrict__ hs_l,
               __half* __restrict__ enc_h, __half* __restrict__ enc_l,
               __half* __restrict__ wq_h, __half* __restrict__ wq_l,
               __half* __restrict__ wk_h, __half* __restrict__ wk_l,
               __half* __restrict__ wv_h, __half* __restrict__ wv_l,
               __half* __restrict__ wo_h, __half* __restrict__ wo_l)
{
    size_t i = ((size_t)blockIdx.x * 256 + threadIdx.x) * 4;
    if (i >= SPLIT_TOT) return;
    const float* src; __half *hi, *lo; size_t base;
    if      (i < NA4)           { src = hs;  hi = hs_h;  lo = hs_l;  base = 0; }
    else if (i < 2 * NA4)       { src = enc; hi = enc_h; lo = enc_l; base = NA4; }
    else if (i < 2 * NA4 + NW4) { src = wq;  hi = wq_h;  lo = wq_l;  base = 2 * NA4; }
    else if (i < 2 * NA4 + 2 * NW4) { src = wk; hi = wk_h; lo = wk_l; base = 2 * NA4 + NW4; }
    else if (i < 2 * NA4 + 3 * NW4) { src = wv; hi = wv_h; lo = wv_l; base = 2 * NA4 + 2 * NW4; }
    else                        { src = wo;  hi = wo_h;  lo = wo_l;  base = 2 * NA4 + 3 * NW4; }
    const size_t j = i - base;
    float4 v[4];
    #pragma unroll
    for (int u = 0; u < 4; ++u) v[u] = ((const float4*)src)[j + u];
    #pragma unroll
    for (int u = 0; u < 4; ++u) {
        uint32_t h0, l0, h1, l1;
        split_pack(v[u].x, v[u].y, h0, l0);
        split_pack(v[u].z, v[u].w, h1, l1);
        ((uint32_t*)hi)[2 * (j + u)]     = h0;
        ((uint32_t*)hi)[2 * (j + u) + 1] = h1;
        ((uint32_t*)lo)[2 * (j + u)]     = l0;
        ((uint32_t*)lo)[2 * (j + u) + 1] = l1;
    }
}

// ---------------------------------------------------------------------------
// fp16 split GEMM, 2 or 3 passes.  128x128 CTA tile, BK=32, 4 warps (64x64
// warp tile), 2-stage cp.async, 2 CTAs/SM.  npass==3: Ah*Bh + Al*Bh + Ah*Bl.
// npass==2: Ah*Bh + Al*Bh (B-lo dropped; error ~2^-11, linear paths only).
// ---------------------------------------------------------------------------
#define TILE_B 10240
#define STAGE_B (4 * TILE_B)
#define SMEM_GEMM (2 * STAGE_B)        // 81920 -> 2 CTAs/SM
#define NSTAGES (KK / 32)
#define GTHREADS 128

__device__ __forceinline__ void load_stage_g(
    uint32_t sbuf, int s, int m0, int n0,
    const __half* __restrict__ Ah, const __half* __restrict__ Al,
    const __half* __restrict__ Wh, const __half* __restrict__ Wl, int tid)
{
    const int k0 = s * 32;
    #pragma unroll
    for (int q = 0; q < 4; ++q) {
        const int id = tid + GTHREADS * q;      // 0..511
        const int r = id >> 2, c = id & 3;
        const uint32_t doff = r * 80 + c * 16;
        const size_t gA = (size_t)(m0 + r) * KK + k0 + c * 8;
        const size_t gW = (size_t)(n0 + r) * KK + k0 + c * 8;
        cp_async16(sbuf + doff,              Ah + gA);
        cp_async16(sbuf + TILE_B + doff,     Al + gA);
        cp_async16(sbuf + 2 * TILE_B + doff, Wh + gW);
        cp_async16(sbuf + 3 * TILE_B + doff, Wl + gW);
    }
}

template<bool QKV>
__global__ __launch_bounds__(GTHREADS, 2)
void gemm_kernel(const __half* __restrict__ a0h, const __half* __restrict__ a0l,
                 const __half* __restrict__ a1h, const __half* __restrict__ a1l,
                 const __half* __restrict__ wqh, const __half* __restrict__ wql,
                 const __half* __restrict__ wkh, const __half* __restrict__ wkl,
                 const __half* __restrict__ wvh, const __half* __restrict__ wvl,
                 const float* __restrict__ cq, const float* __restrict__ sq,
                 const float* __restrict__ ck, const float* __restrict__ sk,
                 __half* __restrict__ qh, __half* __restrict__ ql,
                 __half* __restrict__ kh, __half* __restrict__ kl,
                 __half* __restrict__ vh,
                 float* __restrict__ fout)
{
    extern __shared__ __align__(128) uint8_t smem_raw[];
    const uint32_t sbase = smem_to_u32(smem_raw);
    const int tid = threadIdx.x;
    const int m0 = blockIdx.y * 128;
    const int n0 = blockIdx.x * 128;
    const int z  = QKV ? blockIdx.z : 0;
    // Q/K projections: 3 passes (feed softmax).  V and O projections: 2 passes.
    const int npass = QKV ? ((z == 2) ? 2 : 3) : 2;

    const __half *Ah, *Al, *Wh, *Wl;
    if (QKV) {
        Ah = (z == 0) ? a0h : a1h;
        Al = (z == 0) ? a0l : a1l;
        Wh = (z == 0) ? wqh : (z == 1) ? wkh : wvh;
        Wl = (z == 0) ? wql : (z == 1) ? wkl : wvl;
    } else {
        Ah = a0h; Al = a0l; Wh = wqh; Wl = wql;
    }

    const int wid = tid >> 5, lid = tid & 31;
    const int wm = wid >> 1, wn = wid & 1;      // 2m x 2n warp grid
    const int g = lid >> 2, t = lid & 3;
    const int lrow = lid & 15;
    const int lcolb = (lid >> 4) * 16;

    float acc[4][8][4];
    #pragma unroll
    for (int mt = 0; mt < 4; ++mt)
        #pragma unroll
        for (int nt = 0; nt < 8; ++nt)
            #pragma unroll
            for (int q = 0; q < 4; ++q) acc[mt][nt][q] = 0.0f;

    load_stage_g(sbase, 0, m0, n0, Ah, Al, Wh, Wl, tid);
    CP_ASYNC_COMMIT();

    for (int s = 0; s < NSTAGES; ++s) {
        if (s + 1 < NSTAGES) {
            load_stage_g(sbase + ((s + 1) & 1) * STAGE_B, s + 1, m0, n0, Ah, Al, Wh, Wl, tid);
            CP_ASYNC_COMMIT();
            CP_ASYNC_WAIT(1);
        } else {
            CP_ASYNC_WAIT(0);
        }
        __syncthreads();

        const uint32_t buf = sbase + (s & 1) * STAGE_B;
        const uint32_t aH = buf, aL = buf + TILE_B;
        const uint32_t bH = buf + 2 * TILE_B, bL = buf + 3 * TILE_B;

        #pragma unroll
        for (int kc = 0; kc < 2; ++kc) {
            const uint32_t cb = kc * 32 + lcolb;
            uint32_t ahf[4][4], alf[4][4], bf[4][4];
            #pragma unroll
            for (int mt = 0; mt < 4; ++mt) {
                const uint32_t ro = (wm * 64 + mt * 16 + lrow) * 80 + cb;
                ldm4(ahf[mt], aH + ro);
                ldm4(alf[mt], aL + ro);
            }
            #pragma unroll
            for (int jp = 0; jp < 4; ++jp)
                ldm4(bf[jp], bH + (wn * 64 + jp * 16 + lrow) * 80 + cb);
            // pass 1: Ah*Bh
            #pragma unroll
            for (int jp = 0; jp < 4; ++jp)
                #pragma unroll
                for (int mt = 0; mt < 4; ++mt) {
                    mma16816(acc[mt][2 * jp],     ahf[mt], bf[jp][0], bf[jp][2]);
                    mma16816(acc[mt][2 * jp + 1], ahf[mt], bf[jp][1], bf[jp][3]);
                }
            // pass 2: Al*Bh
            #pragma unroll
            for (int jp = 0; jp < 4; ++jp)
                #pragma unroll
                for (int mt = 0; mt < 4; ++mt) {
                    mma16816(acc[mt][2 * jp],     alf[mt], bf[jp][0], bf[jp][2]);
                    mma16816(acc[mt][2 * jp + 1], alf[mt], bf[jp][1], bf[jp][3]);
                }
            // pass 3 (only npass==3): Ah*Bl
            if (npass == 3) {
                #pragma unroll
                for (int jp = 0; jp < 4; ++jp)
                    ldm4(bf[jp], bL + (wn * 64 + jp * 16 + lrow) * 80 + cb);
                #pragma unroll
                for (int jp = 0; jp < 4; ++jp)
                    #pragma unroll
                    for (int mt = 0; mt < 4; ++mt) {
                        mma16816(acc[mt][2 * jp],     ahf[mt], bf[jp][0], bf[jp][2]);
                        mma16816(acc[mt][2 * jp + 1], ahf[mt], bf[jp][1], bf[jp][3]);
                    }
            }
        }
        __syncthreads();
    }

    // ---------------- epilogue ----------------
    #pragma unroll
    for (int mt = 0; mt < 4; ++mt) {
        #pragma unroll
        for (int rh = 0; rh < 2; ++rh) {
            const int m = m0 + wm * 64 + mt * 16 + g + rh * 8;
            const int tI = m & (TT - 1);
            const int b  = m >> 11;
            #pragma unroll
            for (int nt = 0; nt < 8; ++nt) {
                const int col = wn * 64 + nt * 8 + 2 * t;
                float v0 = acc[mt][nt][rh * 2 + 0];
                float v1 = acc[mt][nt][rh * 2 + 1];
                if (QKV) {
                    if (z < 2) {
                        const float* cT = (z == 0) ? cq : ck;
                        const float* sT = (z == 0) ? sq : sk;
                        const int d2 = col >> 1;
                        const float cs = cT[tI * 64 + d2];
                        const float sn = sT[tI * 64 + d2];
                        const float x0 = v0, x1 = v1;
                        v0 = x0 * cs - x1 * sn;
                        v1 = x1 * cs + x0 * sn;
                    }
                    const int hhead = blockIdx.x;
                    const size_t bh = (size_t)b * HH + hhead;
                    if (z == 2) {
                        // V: single fp16, transposed [B,H,HD,S]
                        const size_t base = (bh * HD + col) * TT + tI;
                        vh[base]      = __float2half(v0);
                        vh[base + TT] = __float2half(v1);
                    } else {
                        const size_t off = (bh * TT + tI) * HD + col;
                        __half* oh = (z == 0) ? qh : kh;
                        __half* ol = (z == 0) ? ql : kl;
                        uint32_t hp, lp;
                        split_pack(v0, v1, hp, lp);
                        *(uint32_t*)(oh + off) = hp;
                        *(uint32_t*)(ol + off) = lp;
                    }
                } else {
                    float* op = fout + (size_t)m * DD + n0 + col;
                    *(float2*)op = make_float2(v0, v1);
                }
            }
        }
    }
}

// ---------------------------------------------------------------------------
// Flash attention: QK^T 3-pass fp16 (scores exact), PV 2-pass (P split
// exactly as fp16 hi/lo, V single fp16).
// smem: Qh/Ql 128x272B; per buf: Kh/Kl 64x272B, Vh 128x144B. Dbl-buffered.
// ---------------------------------------------------------------------------
#define AQ_STR 272
#define AV_STR 144
#define OFF_QL 34816                 // 128*272
#define OFF_KV 69632
#define OFF_KL 17408
#define OFF_VH 34816
#define KV_BUF 53248                 // 2*17408 + 18432
#define ATT_SMEM (OFF_KV + 2 * KV_BUF)   // 176128

__device__ __forceinline__ void load_kv_chunk(
    uint32_t sb, int buf, int chunk, int bh,
    const __half* __restrict__ kh_g, const __half* __restrict__ kl_g,
    const __half* __restrict__ vh_g, int tid)
{
    const uint32_t kb = sb + OFF_KV + buf * KV_BUF;
    const int s0 = chunk * 64;
    #pragma unroll
    for (int i = 0; i < 4; ++i) {
        const int idx = tid + 256 * i;
        const int r = idx >> 4, c2 = idx & 15;  // K: 64 rows x 16 chunks
        const size_t gk = ((size_t)bh * TT + s0 + r) * HD + c2 * 8;
        cp_async16(kb + r * AQ_STR + c2 * 16,          kh_g + gk);
        cp_async16(kb + OFF_KL + r * AQ_STR + c2 * 16, kl_g + gk);
        const int rv = idx >> 3, cv = idx & 7;  // Vt: 128 rows x 8 chunks
        const size_t gv = ((size_t)bh * HD + rv) * TT + s0 + cv * 8;
        cp_async16(kb + OFF_VH + rv * AV_STR + cv * 16, vh_g + gv);
    }
}

__global__ __launch_bounds__(256, 1)
void attn_kernel(const __half* __restrict__ qh_g, const __half* __restrict__ ql_g,
                 const __half* __restrict__ kh_g, const __half* __restrict__ kl_g,
                 const __half* __restrict__ vh_g,
                 __half* __restrict__ ch_g, __half* __restrict__ cl_g)
{
    extern __shared__ __align__(128) uint8_t sm_raw[];
    const uint32_t sb = smem_to_u32(sm_raw);
    const int tid = threadIdx.x;
    const int wid = tid >> 5, lid = tid & 31;
    const int g = lid >> 2, t = lid & 3;
    const int bh = blockIdx.y;
    const int b = bh >> 4, h = bh & 15;
    const int q0 = blockIdx.x * 128;
    const int lrow = lid & 15;
    const int lcolb = (lid >> 4) * 16;

    const size_t qoff = ((size_t)bh * TT + q0) * HD;
    #pragma unroll
    for (int i = 0; i < 8; ++i) {
        const int idx = tid + 256 * i;
        const int r = idx >> 4, c2 = idx & 15;
        const size_t gq = qoff + (size_t)r * HD + c2 * 8;
        cp_async16(sb + r * AQ_STR + c2 * 16,          qh_g + gq);
        cp_async16(sb + OFF_QL + r * AQ_STR + c2 * 16, ql_g + gq);
    }
    load_kv_chunk(sb, 0, 0, bh, kh_g, kl_g, vh_g, tid);
    CP_ASYNC_COMMIT();
    load_kv_chunk(sb, 1, 1, bh, kh_g, kl_g, vh_g, tid);
    CP_ASYNC_COMMIT();

    float O[16][4];
    #pragma unroll
    for (int nv = 0; nv < 16; ++nv)
        #pragma unroll
        for (int q = 0; q < 4; ++q) O[nv][q] = 0.0f;
    float mr0 = -1e30f, mr1 = -1e30f, lr0 = 0.0f, lr1 = 0.0f;

    for (int c = 0; c < 32; ++c) {
        CP_ASYNC_WAIT(1);
        __syncthreads();
        const uint32_t kb = sb + OFF_KV + (c & 1) * KV_BUF;

        // ---- S = Q K^T (fp16 3-pass) ----
        float S[8][4];
        #pragma unroll
        for (int j = 0; j < 8; ++j)
            #pragma unroll
            for (int q = 0; q < 4; ++q) S[j][q] = 0.0f;

        #pragma unroll
        for (int ks = 0; ks < 8; ++ks) {
            const uint32_t cb = ks * 32 + lcolb;
            uint32_t qhf[4], qlf[4], kf[4][4];
            const uint32_t qo = (wid * 16 + lrow) * AQ_STR + cb;
            ldm4(qhf, sb + qo);
            ldm4(qlf, sb + OFF_QL + qo);
            #pragma unroll
            for (int jp = 0; jp < 4; ++jp)
                ldm4(kf[jp], kb + (jp * 16 + lrow) * AQ_STR + cb);
            #pragma unroll
            for (int jp = 0; jp < 4; ++jp) {
                mma16816(S[2 * jp],     qhf, kf[jp][0], kf[jp][2]);
                mma16816(S[2 * jp + 1], qhf, kf[jp][1], kf[jp][3]);
            }
            #pragma unroll
            for (int jp = 0; jp < 4; ++jp) {
                mma16816(S[2 * jp],     qlf, kf[jp][0], kf[jp][2]);
                mma16816(S[2 * jp + 1], qlf, kf[jp][1], kf[jp][3]);
            }
            #pragma unroll
            for (int jp = 0; jp < 4; ++jp)
                ldm4(kf[jp], kb + OFF_KL + (jp * 16 + lrow) * AQ_STR + cb);
            #pragma unroll
            for (int jp = 0; jp < 4; ++jp) {
                mma16816(S[2 * jp],     qhf, kf[jp][0], kf[jp][2]);
                mma16816(S[2 * jp + 1], qhf, kf[jp][1], kf[jp][3]);
            }
        }

        // ---- online softmax ----
        float mx0 = -1e30f, mx1 = -1e30f;
        #pragma unroll
        for (int j = 0; j < 8; ++j) {
            #pragma unroll
            for (int q = 0; q < 4; ++q) S[j][q] *= SCALE;
            mx0 = fmaxf(mx0, fmaxf(S[j][0], S[j][1]));
            mx1 = fmaxf(mx1, fmaxf(S[j][2], S[j][3]));
        }
        mx0 = fmaxf(mx0, __shfl_xor_sync(0xffffffffu, mx0, 1));
        mx0 = fmaxf(mx0, __shfl_xor_sync(0xffffffffu, mx0, 2));
        mx1 = fmaxf(mx1, __shfl_xor_sync(0xffffffffu, mx1, 1));
        mx1 = fmaxf(mx1, __shfl_xor_sync(0xffffffffu, mx1, 2));
        const float mn0 = fmaxf(mr0, mx0), mn1 = fmaxf(mr1, mx1);
        const float cr0 = __expf(mr0 - mn0), cr1 = __expf(mr1 - mn1);
        mr0 = mn0; mr1 = mn1;
        float ls0 = 0.0f, ls1 = 0.0f;
        #pragma unroll
        for (int j = 0; j < 8; ++j) {
            S[j][0] = __expf(S[j][0] - mn0);
            S[j][1] = __expf(S[j][1] - mn0);
            S[j][2] = __expf(S[j][2] - mn1);
            S[j][3] = __expf(S[j][3] - mn1);
            ls0 += S[j][0] + S[j][1];
            ls1 += S[j][2] + S[j][3];
        }
        ls0 += __shfl_xor_sync(0xffffffffu, ls0, 1);
        ls0 += __shfl_xor_sync(0xffffffffu, ls0, 2);
        ls1 += __shfl_xor_sync(0xffffffffu, ls1, 1);
        ls1 += __shfl_xor_sync(0xffffffffu, ls1, 2);
        lr0 = lr0 * cr0 + ls0;
        lr1 = lr1 * cr1 + ls1;
        #pragma unroll
        for (int nv = 0; nv < 16; ++nv) {
            O[nv][0] *= cr0; O[nv][1] *= cr0;
            O[nv][2] *= cr1; O[nv][3] *= cr1;
        }

        // ---- P fragments (fp16 hi/lo; exact to 2^-22) ----
        uint32_t ph[4][4], pl[4][4];
        #pragma unroll
        for (int kk = 0; kk < 4; ++kk) {
            split_pack(S[2 * kk][0],     S[2 * kk][1],     ph[kk][0], pl[kk][0]);
            split_pack(S[2 * kk][2],     S[2 * kk][3],     ph[kk][1], pl[kk][1]);
            split_pack(S[2 * kk + 1][0], S[2 * kk + 1][1], ph[kk][2], pl[kk][2]);
            split_pack(S[2 * kk + 1][2], S[2 * kk + 1][3], ph[kk][3], pl[kk][3]);
        }

        // ---- O += P V (2-pass: Ph*Vh + Pl*Vh) ----
        const uint32_t vbh = kb + OFF_VH;
        #pragma unroll
        for (int kk = 0; kk < 4; ++kk) {
            const uint32_t cb = kk * 32 + lcolb;
            #pragma unroll
            for (int half = 0; half < 2; ++half) {
                uint32_t vf[4][4];
                #pragma unroll
                for (int u = 0; u < 4; ++u)
                    ldm4(vf[u], vbh + ((half * 4 + u) * 16 + lrow) * AV_STR + cb);
                #pragma unroll
                for (int u = 0; u < 4; ++u) {
                    const int np = half * 4 + u;
                    mma16816(O[2 * np],     ph[kk], vf[u][0], vf[u][2]);
                    mma16816(O[2 * np + 1], ph[kk], vf[u][1], vf[u][3]);
                }
                #pragma unroll
                for (int u = 0; u < 4; ++u) {
                    const int np = half * 4 + u;
                    mma16816(O[2 * np],     pl[kk], vf[u][0], vf[u][2]);
                    mma16816(O[2 * np + 1], pl[kk], vf[u][1], vf[u][3]);
                }
            }
        }

        __syncthreads();
        if (c + 2 < 32)
            load_kv_chunk(sb, c & 1, c + 2, bh, kh_g, kl_g, vh_g, tid);
        CP_ASYNC_COMMIT();
    }

    // ---- epilogue: ctx as fp16 hi/lo ----
    const float inv0 = 1.0f / lr0, inv1 = 1.0f / lr1;
    const int t0 = q0 + wid * 16 + g;
    const int t1 = t0 + 8;
    #pragma unroll
    for (int nv = 0; nv < 16; ++nv) {
        const int d = h * HD + nv * 8 + 2 * t;
        const size_t o0 = ((size_t)b * TT + t0) * DD + d;
        const size_t o1 = ((size_t)b * TT + t1) * DD + d;
        uint32_t hp, lp;
        split_pack(O[nv][0] * inv0, O[nv][1] * inv0, hp, lp);
        *(uint32_t*)(ch_g + o0) = hp;
        *(uint32_t*)(cl_g + o0) = lp;
        split_pack(O[nv][2] * inv1, O[nv][3] * inv1, hp, lp);
        *(uint32_t*)(ch_g + o1) = hp;
        *(uint32_t*)(cl_g + o1) = lp;
    }
}

// ---------------------------------------------------------------------------
extern "C" void kernel_launch(void* const* d_in, const int* in_sizes, int n_in,
                              void* d_out, int out_size)
{
    const float* hs  = (const float*)d_in[0];
    const float* enc = (const float*)d_in[1];
    const float* Wq  = (const float*)d_in[2];
    const float* Wk  = (const float*)d_in[3];
    const float* Wv  = (const float*)d_in[4];
    const float* Wo  = (const float*)d_in[5];
    const float* cq  = (const float*)d_in[6];
    const float* sq  = (const float*)d_in[7];
    const float* ck  = (const float*)d_in[8];
    const float* sk  = (const float*)d_in[9];

    __half *hs_h, *hs_l, *enc_h, *enc_l;
    __half *wq_h, *wq_l, *wk_h, *wk_l, *wv_h, *wv_l, *wo_h, *wo_l;
    __half *q_h, *q_l, *k_h, *k_l, *v_h, *c_h, *c_l;
    cudaGetSymbolAddress((void**)&hs_h,  g_hs_h);  cudaGetSymbolAddress((void**)&hs_l,  g_hs_l);
    cudaGetSymbolAddress((void**)&enc_h, g_enc_h); cudaGetSymbolAddress((void**)&enc_l, g_enc_l);
    cudaGetSymbolAddress((void**)&wq_h,  g_wq_h);  cudaGetSymbolAddress((void**)&wq_l,  g_wq_l);
    cudaGetSymbolAddress((void**)&wk_h,  g_wk_h);  cudaGetSymbolAddress((void**)&wk_l,  g_wk_l);
    cudaGetSymbolAddress((void**)&wv_h,  g_wv_h);  cudaGetSymbolAddress((void**)&wv_l,  g_wv_l);
    cudaGetSymbolAddress((void**)&wo_h,  g_wo_h);  cudaGetSymbolAddress((void**)&wo_l,  g_wo_l);
    cudaGetSymbolAddress((void**)&q_h, g_q_h); cudaGetSymbolAddress((void**)&q_l, g_q_l);
    cudaGetSymbolAddress((void**)&k_h, g_k_h); cudaGetSymbolAddress((void**)&k_l, g_k_l);
    cudaGetSymbolAddress((void**)&v_h, g_v_h);
    cudaGetSymbolAddress((void**)&c_h, g_c_h); cudaGetSymbolAddress((void**)&c_l, g_c_l);

    {
        const size_t nthreads = SPLIT_TOT / 4;
        split_all<<<(unsigned)((nthreads + 255) / 256), 256>>>(
            hs, enc, Wq, Wk, Wv, Wo,
            hs_h, hs_l, enc_h, enc_l, wq_h, wq_l, wk_h, wk_l, wv_h, wv_l, wo_h, wo_l);
    }

    cudaFuncSetAttribute(gemm_kernel<true>,
                         cudaFuncAttributeMaxDynamicSharedMemorySize, SMEM_GEMM);
    cudaFuncSetAttribute(gemm_kernel<false>,
                         cudaFuncAttributeMaxDynamicSharedMemorySize, SMEM_GEMM);
    cudaFuncSetAttribute(attn_kernel,
                         cudaFuncAttributeMaxDynamicSharedMemorySize, ATT_SMEM);

    // Q/K/V projections (+RoPE, +head split, +V transpose)
    gemm_kernel<true><<<dim3(DD / 128, MM / 128, 3), GTHREADS, SMEM_GEMM>>>(
        hs_h, hs_l, enc_h, enc_l, wq_h, wq_l, wk_h, wk_l, wv_h, wv_l,
        cq, sq, ck, sk, q_h, q_l, k_h, k_l, v_h, nullptr);

    // Attention
    attn_kernel<<<dim3(TT / 128, BB * HH), 256, ATT_SMEM>>>(
        q_h, q_l, k_h, k_l, v_h, c_h, c_l);

    // Output projection (fp32 out, 2-pass)
    gemm_kernel<false><<<dim3(DD / 128, MM / 128, 1), GTHREADS, SMEM_GEMM>>>(
        c_h, c_l, nullptr, nullptr, wo_h, wo_l, nullptr, nullptr, nullptr, nullptr,
        nullptr, nullptr, nullptr, nullptr,
        nullptr, nullptr, nullptr, nullptr, nullptr, (float*)d_out);
}

// round 9
// speedup vs baseline: 1.4130x; 1.2544x over previous
#include <cuda_runtime.h>
#include <cuda_fp16.h>
#include <cstdint>
#include <cstddef>
#include <math.h>

// ---------------------------------------------------------------------------
#define BB 2
#define HH 16
#define TT 2048
#define DD 2048
#define HD 128
#define KK 2048
#define MM 4096
#define SCALE 0.08838834764831845f
#define CH (BB * HH * TT * HD)

// ---------------------------------------------------------------------------
// Scratch (device globals; allocation is forbidden)
// ---------------------------------------------------------------------------
__device__ __half g_hs_h[MM * KK],  g_hs_l[MM * KK];
__device__ __half g_enc_h[MM * KK], g_enc_l[MM * KK];
__device__ __half g_wq_h[DD * KK];
__device__ __half g_wk_h[DD * KK];
__device__ __half g_wv_h[DD * KK];
__device__ __half g_wo_h[DD * KK];
__device__ __half g_q_h[CH], g_q_l[CH];     // [B,H,T,HD] hi/lo
__device__ __half g_k_h[CH];                // [B,H,S,HD] single fp16
__device__ __half g_v_h[CH];                // [B,H,HD,S] transposed, single fp16
__device__ __half g_c_h[MM * DD], g_c_l[MM * DD];   // ctx [B,T,D] hi/lo

// ---------------------------------------------------------------------------
// Helpers (baseline sm_80 features only)
// ---------------------------------------------------------------------------
__device__ __forceinline__ uint32_t smem_to_u32(const void* p) {
    uint32_t a;
    asm("{ .reg .u64 t; cvta.to.shared.u64 t, %1; cvt.u32.u64 %0, t; }" : "=r"(a) : "l"(p));
    return a;
}
__device__ __forceinline__ void cp_async16(uint32_t dst, const void* src) {
    asm volatile("cp.async.cg.shared.global [%0], [%1], 16;" :: "r"(dst), "l"(src));
}
#define CP_ASYNC_COMMIT() asm volatile("cp.async.commit_group;" ::: "memory")
#define CP_ASYNC_WAIT(n)  asm volatile("cp.async.wait_group %0;" :: "n"(n) : "memory")

__device__ __forceinline__ void ldm4(uint32_t* r, uint32_t addr) {
    asm volatile("ldmatrix.sync.aligned.m8n8.x4.shared.b16 {%0,%1,%2,%3}, [%4];"
                 : "=r"(r[0]), "=r"(r[1]), "=r"(r[2]), "=r"(r[3]) : "r"(addr));
}
__device__ __forceinline__ void mma16816(float* c, const uint32_t* a, uint32_t b0, uint32_t b1) {
    asm volatile("mma.sync.aligned.m16n8k16.row.col.f32.f16.f16.f32 "
                 "{%0,%1,%2,%3}, {%4,%5,%6,%7}, {%8,%9}, {%0,%1,%2,%3};"
                 : "+f"(c[0]), "+f"(c[1]), "+f"(c[2]), "+f"(c[3])
                 : "r"(a[0]), "r"(a[1]), "r"(a[2]), "r"(a[3]), "r"(b0), "r"(b1));
}
__device__ __forceinline__ uint32_t packhf(__half a, __half b) {
    __half2 t(a, b);
    return *reinterpret_cast<uint32_t*>(&t);
}
__device__ __forceinline__ void split_pack(float x, float y, uint32_t& hp, uint32_t& lp) {
    __half hx = __float2half(x), hy = __float2half(y);
    __half lx = __float2half(x - __half2float(hx));
    __half ly = __float2half(y - __half2float(hy));
    hp = packhf(hx, hy); lp = packhf(lx, ly);
}

// ---------------------------------------------------------------------------
// Fused fp32 -> fp16 split: activations hi+lo, weights hi only
// ---------------------------------------------------------------------------
#define NA4 ((size_t)MM * KK / 4)
#define NW4 ((size_t)DD * KK / 4)
#define SPLIT_TOT (2 * NA4 + 4 * NW4)

__global__ __launch_bounds__(256)
void split_all(const float* __restrict__ hs, const float* __restrict__ enc,
               const float* __restrict__ wq, const float* __restrict__ wk,
               const float* __restrict__ wv, const float* __restrict__ wo,
               __half* __restrict__ hs_h, __half* __restrict__ hs_l,
               __half* __restrict__ enc_h, __half* __restrict__ enc_l,
               __half* __restrict__ wq_h, __half* __restrict__ wk_h,
               __half* __restrict__ wv_h, __half* __restrict__ wo_h)
{
    size_t i = ((size_t)blockIdx.x * 256 + threadIdx.x) * 4;
    if (i >= SPLIT_TOT) return;
    const float* src; __half *hi, *lo; size_t base;
    if      (i < NA4)           { src = hs;  hi = hs_h;  lo = hs_l;  base = 0; }
    else if (i < 2 * NA4)       { src = enc; hi = enc_h; lo = enc_l; base = NA4; }
    else if (i < 2 * NA4 + NW4) { src = wq;  hi = wq_h;  lo = nullptr; base = 2 * NA4; }
    else if (i < 2 * NA4 + 2 * NW4) { src = wk; hi = wk_h; lo = nullptr; base = 2 * NA4 + NW4; }
    else if (i < 2 * NA4 + 3 * NW4) { src = wv; hi = wv_h; lo = nullptr; base = 2 * NA4 + 2 * NW4; }
    else                        { src = wo;  hi = wo_h;  lo = nullptr; base = 2 * NA4 + 3 * NW4; }
    const size_t j = i - base;
    float4 v[4];
    #pragma unroll
    for (int u = 0; u < 4; ++u) v[u] = ((const float4*)src)[j + u];
    #pragma unroll
    for (int u = 0; u < 4; ++u) {
        uint32_t h0, l0, h1, l1;
        split_pack(v[u].x, v[u].y, h0, l0);
        split_pack(v[u].z, v[u].w, h1, l1);
        ((uint32_t*)hi)[2 * (j + u)]     = h0;
        ((uint32_t*)hi)[2 * (j + u) + 1] = h1;
        if (lo) {
            ((uint32_t*)lo)[2 * (j + u)]     = l0;
            ((uint32_t*)lo)[2 * (j + u) + 1] = l1;
        }
    }
}

// ---------------------------------------------------------------------------
// 2-pass fp16 GEMM: out = (Ah + Al) * Wh^T.  128x128 CTA tile, BK=32,
// 4 warps (64x64 warp tile), 3-stage cp.async (30KB/stage), 2 CTAs/SM.
// ---------------------------------------------------------------------------
#define TILE_B 10240
#define STAGE_B (3 * TILE_B)           // Ah, Al, Wh
#define SMEM_GEMM (3 * STAGE_B)        // 92160 -> 2 CTAs/SM
#define NSTAGES (KK / 32)
#define GTHREADS 128

__device__ __forceinline__ void load_stage_g(
    uint32_t sbuf, int s, int m0, int n0,
    const __half* __restrict__ Ah, const __half* __restrict__ Al,
    const __half* __restrict__ Wh, int tid)
{
    const int k0 = s * 32;
    #pragma unroll
    for (int q = 0; q < 4; ++q) {
        const int id = tid + GTHREADS * q;      // 0..511
        const int r = id >> 2, c = id & 3;
        const uint32_t doff = r * 80 + c * 16;
        const size_t gA = (size_t)(m0 + r) * KK + k0 + c * 8;
        const size_t gW = (size_t)(n0 + r) * KK + k0 + c * 8;
        cp_async16(sbuf + doff,              Ah + gA);
        cp_async16(sbuf + TILE_B + doff,     Al + gA);
        cp_async16(sbuf + 2 * TILE_B + doff, Wh + gW);
    }
}

template<bool QKV>
__global__ __launch_bounds__(GTHREADS, 2)
void gemm_kernel(const __half* __restrict__ a0h, const __half* __restrict__ a0l,
                 const __half* __restrict__ a1h, const __half* __restrict__ a1l,
                 const __half* __restrict__ w0, const __half* __restrict__ w1,
                 const __half* __restrict__ w2,
                 const float* __restrict__ cq, const float* __restrict__ sq,
                 const float* __restrict__ ck, const float* __restrict__ sk,
                 __half* __restrict__ qh, __half* __restrict__ ql,
                 __half* __restrict__ kh, __half* __restrict__ vh,
                 float* __restrict__ fout)
{
    extern __shared__ __align__(128) uint8_t smem_raw[];
    const uint32_t sbase = smem_to_u32(smem_raw);
    const int tid = threadIdx.x;
    const int m0 = blockIdx.y * 128;
    const int n0 = blockIdx.x * 128;
    const int z  = QKV ? blockIdx.z : 0;

    const __half *Ah, *Al, *Wh;
    if (QKV) {
        Ah = (z == 0) ? a0h : a1h;
        Al = (z == 0) ? a0l : a1l;
        Wh = (z == 0) ? w0 : (z == 1) ? w1 : w2;
    } else {
        Ah = a0h; Al = a0l; Wh = w0;
    }

    const int wid = tid >> 5, lid = tid & 31;
    const int wm = wid >> 1, wn = wid & 1;
    const int g = lid >> 2, t = lid & 3;
    const int lrow = lid & 15;
    const int lcolb = (lid >> 4) * 16;

    float acc[4][8][4];
    #pragma unroll
    for (int mt = 0; mt < 4; ++mt)
        #pragma unroll
        for (int nt = 0; nt < 8; ++nt)
            #pragma unroll
            for (int q = 0; q < 4; ++q) acc[mt][nt][q] = 0.0f;

    load_stage_g(sbase, 0, m0, n0, Ah, Al, Wh, tid); CP_ASYNC_COMMIT();
    load_stage_g(sbase + STAGE_B, 1, m0, n0, Ah, Al, Wh, tid); CP_ASYNC_COMMIT();

    for (int s = 0; s < NSTAGES; ++s) {
        CP_ASYNC_WAIT(1);
        __syncthreads();
        if (s + 2 < NSTAGES) {
            int bslot = (s + 2) % 3;
            load_stage_g(sbase + bslot * STAGE_B, s + 2, m0, n0, Ah, Al, Wh, tid);
        }
        CP_ASYNC_COMMIT();

        const uint32_t buf = sbase + (s % 3) * STAGE_B;
        const uint32_t aH = buf, aL = buf + TILE_B, bH = buf + 2 * TILE_B;

        #pragma unroll
        for (int kc = 0; kc < 2; ++kc) {
            const uint32_t cb = kc * 32 + lcolb;
            uint32_t ahf[4][4], alf[4][4], bf[4][4];
            #pragma unroll
            for (int mt = 0; mt < 4; ++mt) {
                const uint32_t ro = (wm * 64 + mt * 16 + lrow) * 80 + cb;
                ldm4(ahf[mt], aH + ro);
                ldm4(alf[mt], aL + ro);
            }
            #pragma unroll
            for (int jp = 0; jp < 4; ++jp)
                ldm4(bf[jp], bH + (wn * 64 + jp * 16 + lrow) * 80 + cb);
            // pass 1: Ah*Wh
            #pragma unroll
            for (int jp = 0; jp < 4; ++jp)
                #pragma unroll
                for (int mt = 0; mt < 4; ++mt) {
                    mma16816(acc[mt][2 * jp],     ahf[mt], bf[jp][0], bf[jp][2]);
                    mma16816(acc[mt][2 * jp + 1], ahf[mt], bf[jp][1], bf[jp][3]);
                }
            // pass 2: Al*Wh
            #pragma unroll
            for (int jp = 0; jp < 4; ++jp)
                #pragma unroll
                for (int mt = 0; mt < 4; ++mt) {
                    mma16816(acc[mt][2 * jp],     alf[mt], bf[jp][0], bf[jp][2]);
                    mma16816(acc[mt][2 * jp + 1], alf[mt], bf[jp][1], bf[jp][3]);
                }
        }
    }

    // ---------------- epilogue ----------------
    #pragma unroll
    for (int mt = 0; mt < 4; ++mt) {
        #pragma unroll
        for (int rh = 0; rh < 2; ++rh) {
            const int m = m0 + wm * 64 + mt * 16 + g + rh * 8;
            const int tI = m & (TT - 1);
            const int b  = m >> 11;
            #pragma unroll
            for (int nt = 0; nt < 8; ++nt) {
                const int col = wn * 64 + nt * 8 + 2 * t;
                float v0 = acc[mt][nt][rh * 2 + 0];
                float v1 = acc[mt][nt][rh * 2 + 1];
                if (QKV) {
                    if (z < 2) {
                        const float* cT = (z == 0) ? cq : ck;
                        const float* sT = (z == 0) ? sq : sk;
                        const int d2 = col >> 1;
                        const float cs = cT[tI * 64 + d2];
                        const float sn = sT[tI * 64 + d2];
                        const float x0 = v0, x1 = v1;
                        v0 = x0 * cs - x1 * sn;
                        v1 = x1 * cs + x0 * sn;
                    }
                    const int hhead = blockIdx.x;
                    const size_t bh = (size_t)b * HH + hhead;
                    if (z == 0) {
                        const size_t off = (bh * TT + tI) * HD + col;
                        uint32_t hp, lp;
                        split_pack(v0, v1, hp, lp);
                        *(uint32_t*)(qh + off) = hp;
                        *(uint32_t*)(ql + off) = lp;
                    } else if (z == 1) {
                        const size_t off = (bh * TT + tI) * HD + col;
                        *(uint32_t*)(kh + off) = packhf(__float2half(v0), __float2half(v1));
                    } else {
                        const size_t base = (bh * HD + col) * TT + tI;
                        vh[base]      = __float2half(v0);
                        vh[base + TT] = __float2half(v1);
                    }
                } else {
                    float* op = fout + (size_t)m * DD + n0 + col;
                    *(float2*)op = make_float2(v0, v1);
                }
            }
        }
    }
}

// ---------------------------------------------------------------------------
// Flash attention: QK^T 2-pass ((Qh+Ql)*Kh), PV 2-pass ((Ph+Pl)*Vh).
// smem: Qh/Ql 128x272B; per buf: Kh 64x272B + Vh 128x144B. Dbl-buffered.
// ---------------------------------------------------------------------------
#define AQ_STR 272
#define AV_STR 144
#define OFF_QL 34816                 // 128*272
#define OFF_KV 69632
#define OFF_VH 17408                 // within buf: after Kh
#define KV_BUF 35840                 // 17408 + 18432
#define ATT_SMEM (OFF_KV + 2 * KV_BUF)   // 141312

__device__ __forceinline__ void load_kv_chunk(
    uint32_t sb, int buf, int chunk, int bh,
    const __half* __restrict__ kh_g, const __half* __restrict__ vh_g, int tid)
{
    const uint32_t kb = sb + OFF_KV + buf * KV_BUF;
    const int s0 = chunk * 64;
    #pragma unroll
    for (int i = 0; i < 4; ++i) {
        const int idx = tid + 256 * i;
        const int r = idx >> 4, c2 = idx & 15;  // K: 64 rows x 16 chunks
        const size_t gk = ((size_t)bh * TT + s0 + r) * HD + c2 * 8;
        cp_async16(kb + r * AQ_STR + c2 * 16, kh_g + gk);
        const int rv = idx >> 3, cv = idx & 7;  // Vt: 128 rows x 8 chunks
        const size_t gv = ((size_t)bh * HD + rv) * TT + s0 + cv * 8;
        cp_async16(kb + OFF_VH + rv * AV_STR + cv * 16, vh_g + gv);
    }
}

__global__ __launch_bounds__(256, 1)
void attn_kernel(const __half* __restrict__ qh_g, const __half* __restrict__ ql_g,
                 const __half* __restrict__ kh_g, const __half* __restrict__ vh_g,
                 __half* __restrict__ ch_g, __half* __restrict__ cl_g)
{
    extern __shared__ __align__(128) uint8_t sm_raw[];
    const uint32_t sb = smem_to_u32(sm_raw);
    const int tid = threadIdx.x;
    const int wid = tid >> 5, lid = tid & 31;
    const int g = lid >> 2, t = lid & 3;
    const int bh = blockIdx.y;
    const int b = bh >> 4, h = bh & 15;
    const int q0 = blockIdx.x * 128;
    const int lrow = lid & 15;
    const int lcolb = (lid >> 4) * 16;

    const size_t qoff = ((size_t)bh * TT + q0) * HD;
    #pragma unroll
    for (int i = 0; i < 8; ++i) {
        const int idx = tid + 256 * i;
        const int r = idx >> 4, c2 = idx & 15;
        const size_t gq = qoff + (size_t)r * HD + c2 * 8;
        cp_async16(sb + r * AQ_STR + c2 * 16,          qh_g + gq);
        cp_async16(sb + OFF_QL + r * AQ_STR + c2 * 16, ql_g + gq);
    }
    load_kv_chunk(sb, 0, 0, bh, kh_g, vh_g, tid);
    CP_ASYNC_COMMIT();
    load_kv_chunk(sb, 1, 1, bh, kh_g, vh_g, tid);
    CP_ASYNC_COMMIT();

    float O[16][4];
    #pragma unroll
    for (int nv = 0; nv < 16; ++nv)
        #pragma unroll
        for (int q = 0; q < 4; ++q) O[nv][q] = 0.0f;
    float mr0 = -1e30f, mr1 = -1e30f, lr0 = 0.0f, lr1 = 0.0f;

    for (int c = 0; c < 32; ++c) {
        CP_ASYNC_WAIT(1);
        __syncthreads();
        const uint32_t kb = sb + OFF_KV + (c & 1) * KV_BUF;

        // ---- S = Q K^T (2-pass) ----
        float S[8][4];
        #pragma unroll
        for (int j = 0; j < 8; ++j)
            #pragma unroll
            for (int q = 0; q < 4; ++q) S[j][q] = 0.0f;

        #pragma unroll
        for (int ks = 0; ks < 8; ++ks) {
            const uint32_t cb = ks * 32 + lcolb;
            uint32_t qhf[4], qlf[4], kf[4][4];
            const uint32_t qo = (wid * 16 + lrow) * AQ_STR + cb;
            ldm4(qhf, sb + qo);
            ldm4(qlf, sb + OFF_QL + qo);
            #pragma unroll
            for (int jp = 0; jp < 4; ++jp)
                ldm4(kf[jp], kb + (jp * 16 + lrow) * AQ_STR + cb);
            #pragma unroll
            for (int jp = 0; jp < 4; ++jp) {
                mma16816(S[2 * jp],     qhf, kf[jp][0], kf[jp][2]);
                mma16816(S[2 * jp + 1], qhf, kf[jp][1], kf[jp][3]);
            }
            #pragma unroll
            for (int jp = 0; jp < 4; ++jp) {
                mma16816(S[2 * jp],     qlf, kf[jp][0], kf[jp][2]);
                mma16816(S[2 * jp + 1], qlf, kf[jp][1], kf[jp][3]);
            }
        }

        // ---- online softmax ----
        float mx0 = -1e30f, mx1 = -1e30f;
        #pragma unroll
        for (int j = 0; j < 8; ++j) {
            #pragma unroll
            for (int q = 0; q < 4; ++q) S[j][q] *= SCALE;
            mx0 = fmaxf(mx0, fmaxf(S[j][0], S[j][1]));
            mx1 = fmaxf(mx1, fmaxf(S[j][2], S[j][3]));
        }
        mx0 = fmaxf(mx0, __shfl_xor_sync(0xffffffffu, mx0, 1));
        mx0 = fmaxf(mx0, __shfl_xor_sync(0xffffffffu, mx0, 2));
        mx1 = fmaxf(mx1, __shfl_xor_sync(0xffffffffu, mx1, 1));
        mx1 = fmaxf(mx1, __shfl_xor_sync(0xffffffffu, mx1, 2));
        const float mn0 = fmaxf(mr0, mx0), mn1 = fmaxf(mr1, mx1);
        const float cr0 = __expf(mr0 - mn0), cr1 = __expf(mr1 - mn1);
        mr0 = mn0; mr1 = mn1;
        float ls0 = 0.0f, ls1 = 0.0f;
        #pragma unroll
        for (int j = 0; j < 8; ++j) {
            S[j][0] = __expf(S[j][0] - mn0);
            S[j][1] = __expf(S[j][1] - mn0);
            S[j][2] = __expf(S[j][2] - mn1);
            S[j][3] = __expf(S[j][3] - mn1);
            ls0 += S[j][0] + S[j][1];
            ls1 += S[j][2] + S[j][3];
        }
        ls0 += __shfl_xor_sync(0xffffffffu, ls0, 1);
        ls0 += __shfl_xor_sync(0xffffffffu, ls0, 2);
        ls1 += __shfl_xor_sync(0xffffffffu, ls1, 1);
        ls1 += __shfl_xor_sync(0xffffffffu, ls1, 2);
        lr0 = lr0 * cr0 + ls0;
        lr1 = lr1 * cr1 + ls1;
        #pragma unroll
        for (int nv = 0; nv < 16; ++nv) {
            O[nv][0] *= cr0; O[nv][1] *= cr0;
            O[nv][2] *= cr1; O[nv][3] *= cr1;
        }

        // ---- P fragments (fp16 hi/lo; exact to 2^-22) ----
        uint32_t ph[4][4], pl[4][4];
        #pragma unroll
        for (int kk = 0; kk < 4; ++kk) {
            split_pack(S[2 * kk][0],     S[2 * kk][1],     ph[kk][0], pl[kk][0]);
            split_pack(S[2 * kk][2],     S[2 * kk][3],     ph[kk][1], pl[kk][1]);
            split_pack(S[2 * kk + 1][0], S[2 * kk + 1][1], ph[kk][2], pl[kk][2]);
            split_pack(S[2 * kk + 1][2], S[2 * kk + 1][3], ph[kk][3], pl[kk][3]);
        }

        // ---- O += P V (2-pass) ----
        const uint32_t vbh = kb + OFF_VH;
        #pragma unroll
        for (int kk = 0; kk < 4; ++kk) {
            const uint32_t cb = kk * 32 + lcolb;
            #pragma unroll
            for (int half = 0; half < 2; ++half) {
                uint32_t vf[4][4];
                #pragma unroll
                for (int u = 0; u < 4; ++u)
                    ldm4(vf[u], vbh + ((half * 4 + u) * 16 + lrow) * AV_STR + cb);
                #pragma unroll
                for (int u = 0; u < 4; ++u) {
                    const int np = half * 4 + u;
                    mma16816(O[2 * np],     ph[kk], vf[u][0], vf[u][2]);
                    mma16816(O[2 * np + 1], ph[kk], vf[u][1], vf[u][3]);
                }
                #pragma unroll
                for (int u = 0; u < 4; ++u) {
                    const int np = half * 4 + u;
                    mma16816(O[2 * np],     pl[kk], vf[u][0], vf[u][2]);
                    mma16816(O[2 * np + 1], pl[kk], vf[u][1], vf[u][3]);
                }
            }
        }

        __syncthreads();
        if (c + 2 < 32)
            load_kv_chunk(sb, c & 1, c + 2, bh, kh_g, vh_g, tid);
        CP_ASYNC_COMMIT();
    }

    // ---- epilogue: ctx as fp16 hi/lo ----
    const float inv0 = 1.0f / lr0, inv1 = 1.0f / lr1;
    const int t0 = q0 + wid * 16 + g;
    const int t1 = t0 + 8;
    #pragma unroll
    for (int nv = 0; nv < 16; ++nv) {
        const int d = h * HD + nv * 8 + 2 * t;
        const size_t o0 = ((size_t)b * TT + t0) * DD + d;
        const size_t o1 = ((size_t)b * TT + t1) * DD + d;
        uint32_t hp, lp;
        split_pack(O[nv][0] * inv0, O[nv][1] * inv0, hp, lp);
        *(uint32_t*)(ch_g + o0) = hp;
        *(uint32_t*)(cl_g + o0) = lp;
        split_pack(O[nv][2] * inv1, O[nv][3] * inv1, hp, lp);
        *(uint32_t*)(ch_g + o1) = hp;
        *(uint32_t*)(cl_g + o1) = lp;
    }
}

// ---------------------------------------------------------------------------
extern "C" void kernel_launch(void* const* d_in, const int* in_sizes, int n_in,
                              void* d_out, int out_size)
{
    const float* hs  = (const float*)d_in[0];
    const float* enc = (const float*)d_in[1];
    const float* Wq  = (const float*)d_in[2];
    const float* Wk  = (const float*)d_in[3];
    const float* Wv  = (const float*)d_in[4];
    const float* Wo  = (const float*)d_in[5];
    const float* cq  = (const float*)d_in[6];
    const float* sq  = (const float*)d_in[7];
    const float* ck  = (const float*)d_in[8];
    const float* sk  = (const float*)d_in[9];

    __half *hs_h, *hs_l, *enc_h, *enc_l;
    __half *wq_h, *wk_h, *wv_h, *wo_h;
    __half *q_h, *q_l, *k_h, *v_h, *c_h, *c_l;
    cudaGetSymbolAddress((void**)&hs_h,  g_hs_h);  cudaGetSymbolAddress((void**)&hs_l,  g_hs_l);
    cudaGetSymbolAddress((void**)&enc_h, g_enc_h); cudaGetSymbolAddress((void**)&enc_l, g_enc_l);
    cudaGetSymbolAddress((void**)&wq_h,  g_wq_h);
    cudaGetSymbolAddress((void**)&wk_h,  g_wk_h);
    cudaGetSymbolAddress((void**)&wv_h,  g_wv_h);
    cudaGetSymbolAddress((void**)&wo_h,  g_wo_h);
    cudaGetSymbolAddress((void**)&q_h, g_q_h); cudaGetSymbolAddress((void**)&q_l, g_q_l);
    cudaGetSymbolAddress((void**)&k_h, g_k_h);
    cudaGetSymbolAddress((void**)&v_h, g_v_h);
    cudaGetSymbolAddress((void**)&c_h, g_c_h); cudaGetSymbolAddress((void**)&c_l, g_c_l);

    {
        const size_t nthreads = SPLIT_TOT / 4;
        split_all<<<(unsigned)((nthreads + 255) / 256), 256>>>(
            hs, enc, Wq, Wk, Wv, Wo,
            hs_h, hs_l, enc_h, enc_l, wq_h, wk_h, wv_h, wo_h);
    }

    cudaFuncSetAttribute(gemm_kernel<true>,
                         cudaFuncAttributeMaxDynamicSharedMemorySize, SMEM_GEMM);
    cudaFuncSetAttribute(gemm_kernel<false>,
                         cudaFuncAttributeMaxDynamicSharedMemorySize, SMEM_GEMM);
    cudaFuncSetAttribute(attn_kernel,
                         cudaFuncAttributeMaxDynamicSharedMemorySize, ATT_SMEM);

    // Q/K/V projections (+RoPE, +head split, +V transpose)
    gemm_kernel<true><<<dim3(DD / 128, MM / 128, 3), GTHREADS, SMEM_GEMM>>>(
        hs_h, hs_l, enc_h, enc_l, wq_h, wk_h, wv_h,
        cq, sq, ck, sk, q_h, q_l, k_h, v_h, nullptr);

    // Attention
    attn_kernel<<<dim3(TT / 128, BB * HH), 256, ATT_SMEM>>>(
        q_h, q_l, k_h, v_h, c_h, c_l);

    // Output projection (fp32 out)
    gemm_kernel<false><<<dim3(DD / 128, MM / 128, 1), GTHREADS, SMEM_GEMM>>>(
        c_h, c_l, nullptr, nullptr, wo_h, nullptr, nullptr,
        nullptr, nullptr, nullptr, nullptr,
        nullptr, nullptr, nullptr, nullptr, (float*)d_out);
}

// round 10
// speedup vs baseline: 2.4338x; 1.7224x over previous
#include <cuda_runtime.h>
#include <cuda_fp16.h>
#include <cstdint>
#include <cstddef>
#include <math.h>

// ---------------------------------------------------------------------------
#define BB 2
#define HH 16
#define TT 2048
#define DD 2048
#define HD 128
#define KK 2048
#define MM 4096
#define SCALE 0.08838834764831845f
#define CH (BB * HH * TT * HD)

// ---------------------------------------------------------------------------
// Scratch (device globals; allocation is forbidden).  All single fp16.
// ---------------------------------------------------------------------------
__device__ __half g_hs[MM * KK];
__device__ __half g_enc[MM * KK];
__device__ __half g_wq[DD * KK];
__device__ __half g_wk[DD * KK];
__device__ __half g_wv[DD * KK];
__device__ __half g_wo[DD * KK];
__device__ __half g_q[CH];                  // [B,H,T,HD]
__device__ __half g_k[CH];                  // [B,H,S,HD]
__device__ __half g_v[CH];                  // [B,H,HD,S] transposed
__device__ __half g_c[MM * DD];             // ctx [B,T,D]

// ---------------------------------------------------------------------------
// Helpers (baseline sm_80 features only)
// ---------------------------------------------------------------------------
__device__ __forceinline__ uint32_t smem_to_u32(const void* p) {
    uint32_t a;
    asm("{ .reg .u64 t; cvta.to.shared.u64 t, %1; cvt.u32.u64 %0, t; }" : "=r"(a) : "l"(p));
    return a;
}
__device__ __forceinline__ void cp_async16(uint32_t dst, const void* src) {
    asm volatile("cp.async.cg.shared.global [%0], [%1], 16;" :: "r"(dst), "l"(src));
}
#define CP_ASYNC_COMMIT() asm volatile("cp.async.commit_group;" ::: "memory")
#define CP_ASYNC_WAIT(n)  asm volatile("cp.async.wait_group %0;" :: "n"(n) : "memory")

__device__ __forceinline__ void ldm4(uint32_t* r, uint32_t addr) {
    asm volatile("ldmatrix.sync.aligned.m8n8.x4.shared.b16 {%0,%1,%2,%3}, [%4];"
                 : "=r"(r[0]), "=r"(r[1]), "=r"(r[2]), "=r"(r[3]) : "r"(addr));
}
__device__ __forceinline__ void mma16816(float* c, const uint32_t* a, uint32_t b0, uint32_t b1) {
    asm volatile("mma.sync.aligned.m16n8k16.row.col.f32.f16.f16.f32 "
                 "{%0,%1,%2,%3}, {%4,%5,%6,%7}, {%8,%9}, {%0,%1,%2,%3};"
                 : "+f"(c[0]), "+f"(c[1]), "+f"(c[2]), "+f"(c[3])
                 : "r"(a[0]), "r"(a[1]), "r"(a[2]), "r"(a[3]), "r"(b0), "r"(b1));
}
__device__ __forceinline__ uint32_t packhf(__half a, __half b) {
    __half2 t(a, b);
    return *reinterpret_cast<uint32_t*>(&t);
}

// ---------------------------------------------------------------------------
// Fused fp32 -> fp16 convert for all 6 input tensors (single precision)
// ---------------------------------------------------------------------------
#define NAE ((size_t)MM * KK)
#define NWE ((size_t)DD * KK)
#define CONV_TOT ((2 * NAE + 4 * NWE) / 4)   // in float4 units

__global__ __launch_bounds__(256)
void conv_all(const float* __restrict__ hs, const float* __restrict__ enc,
              const float* __restrict__ wq, const float* __restrict__ wk,
              const float* __restrict__ wv, const float* __restrict__ wo,
              __half* __restrict__ hs_o, __half* __restrict__ enc_o,
              __half* __restrict__ wq_o, __half* __restrict__ wk_o,
              __half* __restrict__ wv_o, __half* __restrict__ wo_o)
{
    size_t i = ((size_t)blockIdx.x * 256 + threadIdx.x) * 4;   // first float4
    if (i >= CONV_TOT) return;
    const size_t A4 = NAE / 4, W4 = NWE / 4;
    const float* src; __half* dst; size_t base;
    if      (i < A4)            { src = hs;  dst = hs_o;  base = 0; }
    else if (i < 2 * A4)        { src = enc; dst = enc_o; base = A4; }
    else if (i < 2 * A4 + W4)   { src = wq;  dst = wq_o;  base = 2 * A4; }
    else if (i < 2 * A4 + 2 * W4) { src = wk; dst = wk_o; base = 2 * A4 + W4; }
    else if (i < 2 * A4 + 3 * W4) { src = wv; dst = wv_o; base = 2 * A4 + 2 * W4; }
    else                        { src = wo;  dst = wo_o;  base = 2 * A4 + 3 * W4; }
    const size_t j = i - base;
    #pragma unroll
    for (int u = 0; u < 4; ++u) {
        float4 v = ((const float4*)src)[j + u];
        ((uint32_t*)dst)[2 * (j + u)]     = packhf(__float2half(v.x), __float2half(v.y));
        ((uint32_t*)dst)[2 * (j + u) + 1] = packhf(__float2half(v.z), __float2half(v.w));
    }
}

// ---------------------------------------------------------------------------
// 1-pass fp16 GEMM: out = A * W^T, fp32 accum.  128x128 CTA tile, BK=32,
// 4 warps (64x64 warp tile), 4-stage cp.async (20KB/stage), 2 CTAs/SM.
// ---------------------------------------------------------------------------
#define TILE_B 10240
#define STAGE_B (2 * TILE_B)           // A, W
#define SMEM_GEMM (4 * STAGE_B)        // 81920 -> 2 CTAs/SM
#define NSTAGES (KK / 32)
#define GTHREADS 128

__device__ __forceinline__ void load_stage_g(
    uint32_t sbuf, int s, int m0, int n0,
    const __half* __restrict__ A, const __half* __restrict__ W, int tid)
{
    const int k0 = s * 32;
    #pragma unroll
    for (int q = 0; q < 4; ++q) {
        const int id = tid + GTHREADS * q;      // 0..511
        const int r = id >> 2, c = id & 3;
        const uint32_t doff = r * 80 + c * 16;
        const size_t gA = (size_t)(m0 + r) * KK + k0 + c * 8;
        const size_t gW = (size_t)(n0 + r) * KK + k0 + c * 8;
        cp_async16(sbuf + doff,          A + gA);
        cp_async16(sbuf + TILE_B + doff, W + gW);
    }
}

template<bool QKV>
__global__ __launch_bounds__(GTHREADS, 2)
void gemm_kernel(const __half* __restrict__ a0, const __half* __restrict__ a1,
                 const __half* __restrict__ w0, const __half* __restrict__ w1,
                 const __half* __restrict__ w2,
                 const float* __restrict__ cq, const float* __restrict__ sq,
                 const float* __restrict__ ck, const float* __restrict__ sk,
                 __half* __restrict__ qo, __half* __restrict__ ko,
                 __half* __restrict__ vo,
                 float* __restrict__ fout)
{
    extern __shared__ __align__(128) uint8_t smem_raw[];
    const uint32_t sbase = smem_to_u32(smem_raw);
    const int tid = threadIdx.x;
    const int m0 = blockIdx.y * 128;
    const int n0 = blockIdx.x * 128;
    const int z  = QKV ? blockIdx.z : 0;

    const __half *A, *W;
    if (QKV) {
        A = (z == 0) ? a0 : a1;
        W = (z == 0) ? w0 : (z == 1) ? w1 : w2;
    } else {
        A = a0; W = w0;
    }

    const int wid = tid >> 5, lid = tid & 31;
    const int wm = wid >> 1, wn = wid & 1;
    const int g = lid >> 2, t = lid & 3;
    const int lrow = lid & 15;
    const int lcolb = (lid >> 4) * 16;

    float acc[4][8][4];
    #pragma unroll
    for (int mt = 0; mt < 4; ++mt)
        #pragma unroll
        for (int nt = 0; nt < 8; ++nt)
            #pragma unroll
            for (int q = 0; q < 4; ++q) acc[mt][nt][q] = 0.0f;

    load_stage_g(sbase, 0, m0, n0, A, W, tid); CP_ASYNC_COMMIT();
    load_stage_g(sbase + STAGE_B, 1, m0, n0, A, W, tid); CP_ASYNC_COMMIT();
    load_stage_g(sbase + 2 * STAGE_B, 2, m0, n0, A, W, tid); CP_ASYNC_COMMIT();

    for (int s = 0; s < NSTAGES; ++s) {
        CP_ASYNC_WAIT(2);
        __syncthreads();
        if (s + 3 < NSTAGES)
            load_stage_g(sbase + ((s + 3) & 3) * STAGE_B, s + 3, m0, n0, A, W, tid);
        CP_ASYNC_COMMIT();

        const uint32_t buf = sbase + (s & 3) * STAGE_B;
        const uint32_t aT = buf, bT = buf + TILE_B;

        #pragma unroll
        for (int kc = 0; kc < 2; ++kc) {
            const uint32_t cb = kc * 32 + lcolb;
            uint32_t af[4][4], bf[4][4];
            #pragma unroll
            for (int mt = 0; mt < 4; ++mt)
                ldm4(af[mt], aT + (wm * 64 + mt * 16 + lrow) * 80 + cb);
            #pragma unroll
            for (int jp = 0; jp < 4; ++jp)
                ldm4(bf[jp], bT + (wn * 64 + jp * 16 + lrow) * 80 + cb);
            #pragma unroll
            for (int jp = 0; jp < 4; ++jp)
                #pragma unroll
                for (int mt = 0; mt < 4; ++mt) {
                    mma16816(acc[mt][2 * jp],     af[mt], bf[jp][0], bf[jp][2]);
                    mma16816(acc[mt][2 * jp + 1], af[mt], bf[jp][1], bf[jp][3]);
                }
        }
    }

    // ---------------- epilogue ----------------
    #pragma unroll
    for (int mt = 0; mt < 4; ++mt) {
        #pragma unroll
        for (int rh = 0; rh < 2; ++rh) {
            const int m = m0 + wm * 64 + mt * 16 + g + rh * 8;
            const int tI = m & (TT - 1);
            const int b  = m >> 11;
            #pragma unroll
            for (int nt = 0; nt < 8; ++nt) {
                const int col = wn * 64 + nt * 8 + 2 * t;
                float v0 = acc[mt][nt][rh * 2 + 0];
                float v1 = acc[mt][nt][rh * 2 + 1];
                if (QKV) {
                    if (z < 2) {
                        const float* cT = (z == 0) ? cq : ck;
                        const float* sT = (z == 0) ? sq : sk;
                        const int d2 = col >> 1;
                        const float cs = cT[tI * 64 + d2];
                        const float sn = sT[tI * 64 + d2];
                        const float x0 = v0, x1 = v1;
                        v0 = x0 * cs - x1 * sn;
                        v1 = x1 * cs + x0 * sn;
                    }
                    const int hhead = blockIdx.x;
                    const size_t bh = (size_t)b * HH + hhead;
                    if (z == 2) {
                        const size_t base = (bh * HD + col) * TT + tI;
                        vo[base]      = __float2half(v0);
                        vo[base + TT] = __float2half(v1);
                    } else {
                        const size_t off = (bh * TT + tI) * HD + col;
                        __half* op = (z == 0) ? qo : ko;
                        *(uint32_t*)(op + off) = packhf(__float2half(v0), __float2half(v1));
                    }
                } else {
                    float* op = fout + (size_t)m * DD + n0 + col;
                    *(float2*)op = make_float2(v0, v1);
                }
            }
        }
    }
}

// ---------------------------------------------------------------------------
// Flash attention: all single fp16, QK^T 1-pass, PV 1-pass, fp32 accum +
// fp32 softmax.  smem: Q 128x272B; per buf: K 64x272B + Vt 128x144B.
// ---------------------------------------------------------------------------
#define AQ_STR 272
#define AV_STR 144
#define OFF_KV 34816                 // 128*272 (Q)
#define OFF_VH 17408                 // within buf: after K
#define KV_BUF 35840                 // 17408 + 18432
#define ATT_SMEM (OFF_KV + 2 * KV_BUF)   // 106496

__device__ __forceinline__ void load_kv_chunk(
    uint32_t sb, int buf, int chunk, int bh,
    const __half* __restrict__ k_g, const __half* __restrict__ v_g, int tid)
{
    const uint32_t kb = sb + OFF_KV + buf * KV_BUF;
    const int s0 = chunk * 64;
    #pragma unroll
    for (int i = 0; i < 4; ++i) {
        const int idx = tid + 256 * i;
        const int r = idx >> 4, c2 = idx & 15;  // K: 64 rows x 16 chunks
        const size_t gk = ((size_t)bh * TT + s0 + r) * HD + c2 * 8;
        cp_async16(kb + r * AQ_STR + c2 * 16, k_g + gk);
        const int rv = idx >> 3, cv = idx & 7;  // Vt: 128 rows x 8 chunks
        const size_t gv = ((size_t)bh * HD + rv) * TT + s0 + cv * 8;
        cp_async16(kb + OFF_VH + rv * AV_STR + cv * 16, v_g + gv);
    }
}

__global__ __launch_bounds__(256, 1)
void attn_kernel(const __half* __restrict__ q_g, const __half* __restrict__ k_g,
                 const __half* __restrict__ v_g, __half* __restrict__ c_g)
{
    extern __shared__ __align__(128) uint8_t sm_raw[];
    const uint32_t sb = smem_to_u32(sm_raw);
    const int tid = threadIdx.x;
    const int wid = tid >> 5, lid = tid & 31;
    const int g = lid >> 2, t = lid & 3;
    const int bh = blockIdx.y;
    const int b = bh >> 4, h = bh & 15;
    const int q0 = blockIdx.x * 128;
    const int lrow = lid & 15;
    const int lcolb = (lid >> 4) * 16;

    const size_t qoff = ((size_t)bh * TT + q0) * HD;
    #pragma unroll
    for (int i = 0; i < 4; ++i) {
        const int idx = tid + 256 * i;          // 0..1023
        const int r = idx >> 3, c2 = idx & 7;   // 128 rows x 8 chunks of 16B
        const size_t gq = qoff + (size_t)r * HD + c2 * 16;
        cp_async16(sb + r * AQ_STR + c2 * 32,      q_g + gq);       // low half
        cp_async16(sb + r * AQ_STR + c2 * 32 + 16, q_g + gq + 8);   // high half
    }
    load_kv_chunk(sb, 0, 0, bh, k_g, v_g, tid);
    CP_ASYNC_COMMIT();
    load_kv_chunk(sb, 1, 1, bh, k_g, v_g, tid);
    CP_ASYNC_COMMIT();

    float O[16][4];
    #pragma unroll
    for (int nv = 0; nv < 16; ++nv)
        #pragma unroll
        for (int q = 0; q < 4; ++q) O[nv][q] = 0.0f;
    float mr0 = -1e30f, mr1 = -1e30f, lr0 = 0.0f, lr1 = 0.0f;

    for (int c = 0; c < 32; ++c) {
        CP_ASYNC_WAIT(1);
        __syncthreads();
        const uint32_t kb = sb + OFF_KV + (c & 1) * KV_BUF;

        // ---- S = Q K^T (1-pass fp16) ----
        float S[8][4];
        #pragma unroll
        for (int j = 0; j < 8; ++j)
            #pragma unroll
            for (int q = 0; q < 4; ++q) S[j][q] = 0.0f;

        #pragma unroll
        for (int ks = 0; ks < 8; ++ks) {
            const uint32_t cb = ks * 32 + lcolb;
            uint32_t qf[4], kf[4][4];
            ldm4(qf, sb + (wid * 16 + lrow) * AQ_STR + cb);
            #pragma unroll
            for (int jp = 0; jp < 4; ++jp)
                ldm4(kf[jp], kb + (jp * 16 + lrow) * AQ_STR + cb);
            #pragma unroll
            for (int jp = 0; jp < 4; ++jp) {
                mma16816(S[2 * jp],     qf, kf[jp][0], kf[jp][2]);
                mma16816(S[2 * jp + 1], qf, kf[jp][1], kf[jp][3]);
            }
        }

        // ---- online softmax (fp32) ----
        float mx0 = -1e30f, mx1 = -1e30f;
        #pragma unroll
        for (int j = 0; j < 8; ++j) {
            #pragma unroll
            for (int q = 0; q < 4; ++q) S[j][q] *= SCALE;
            mx0 = fmaxf(mx0, fmaxf(S[j][0], S[j][1]));
            mx1 = fmaxf(mx1, fmaxf(S[j][2], S[j][3]));
        }
        mx0 = fmaxf(mx0, __shfl_xor_sync(0xffffffffu, mx0, 1));
        mx0 = fmaxf(mx0, __shfl_xor_sync(0xffffffffu, mx0, 2));
        mx1 = fmaxf(mx1, __shfl_xor_sync(0xffffffffu, mx1, 1));
        mx1 = fmaxf(mx1, __shfl_xor_sync(0xffffffffu, mx1, 2));
        const float mn0 = fmaxf(mr0, mx0), mn1 = fmaxf(mr1, mx1);
        const float cr0 = __expf(mr0 - mn0), cr1 = __expf(mr1 - mn1);
        mr0 = mn0; mr1 = mn1;
        float ls0 = 0.0f, ls1 = 0.0f;
        #pragma unroll
        for (int j = 0; j < 8; ++j) {
            S[j][0] = __expf(S[j][0] - mn0);
            S[j][1] = __expf(S[j][1] - mn0);
            S[j][2] = __expf(S[j][2] - mn1);
            S[j][3] = __expf(S[j][3] - mn1);
            ls0 += S[j][0] + S[j][1];
            ls1 += S[j][2] + S[j][3];
        }
        ls0 += __shfl_xor_sync(0xffffffffu, ls0, 1);
        ls0 += __shfl_xor_sync(0xffffffffu, ls0, 2);
        ls1 += __shfl_xor_sync(0xffffffffu, ls1, 1);
        ls1 += __shfl_xor_sync(0xffffffffu, ls1, 2);
        lr0 = lr0 * cr0 + ls0;
        lr1 = lr1 * cr1 + ls1;
        #pragma unroll
        for (int nv = 0; nv < 16; ++nv) {
            O[nv][0] *= cr0; O[nv][1] *= cr0;
            O[nv][2] *= cr1; O[nv][3] *= cr1;
        }

        // ---- P fragments (single fp16) ----
        uint32_t pf[4][4];
        #pragma unroll
        for (int kk = 0; kk < 4; ++kk) {
            pf[kk][0] = packhf(__float2half(S[2 * kk][0]),     __float2half(S[2 * kk][1]));
            pf[kk][1] = packhf(__float2half(S[2 * kk][2]),     __float2half(S[2 * kk][3]));
            pf[kk][2] = packhf(__float2half(S[2 * kk + 1][0]), __float2half(S[2 * kk + 1][1]));
            pf[kk][3] = packhf(__float2half(S[2 * kk + 1][2]), __float2half(S[2 * kk + 1][3]));
        }

        // ---- O += P V (1-pass) ----
        const uint32_t vb = kb + OFF_VH;
        #pragma unroll
        for (int kk = 0; kk < 4; ++kk) {
            const uint32_t cb = kk * 32 + lcolb;
            #pragma unroll
            for (int half = 0; half < 2; ++half) {
                uint32_t vf[4][4];
                #pragma unroll
                for (int u = 0; u < 4; ++u)
                    ldm4(vf[u], vb + ((half * 4 + u) * 16 + lrow) * AV_STR + cb);
                #pragma unroll
                for (int u = 0; u < 4; ++u) {
                    const int np = half * 4 + u;
                    mma16816(O[2 * np],     pf[kk], vf[u][0], vf[u][2]);
                    mma16816(O[2 * np + 1], pf[kk], vf[u][1], vf[u][3]);
                }
            }
        }

        __syncthreads();
        if (c + 2 < 32)
            load_kv_chunk(sb, c & 1, c + 2, bh, k_g, v_g, tid);
        CP_ASYNC_COMMIT();
    }

    // ---- epilogue: ctx single fp16 ----
    const float inv0 = 1.0f / lr0, inv1 = 1.0f / lr1;
    const int t0 = q0 + wid * 16 + g;
    const int t1 = t0 + 8;
    #pragma unroll
    for (int nv = 0; nv < 16; ++nv) {
        const int d = h * HD + nv * 8 + 2 * t;
        const size_t o0 = ((size_t)b * TT + t0) * DD + d;
        const size_t o1 = ((size_t)b * TT + t1) * DD + d;
        *(uint32_t*)(c_g + o0) =
            packhf(__float2half(O[nv][0] * inv0), __float2half(O[nv][1] * inv0));
        *(uint32_t*)(c_g + o1) =
            packhf(__float2half(O[nv][2] * inv1), __float2half(O[nv][3] * inv1));
    }
}

// ---------------------------------------------------------------------------
extern "C" void kernel_launch(void* const* d_in, const int* in_sizes, int n_in,
                              void* d_out, int out_size)
{
    const float* hs  = (const float*)d_in[0];
    const float* enc = (const float*)d_in[1];
    const float* Wq  = (const float*)d_in[2];
    const float* Wk  = (const float*)d_in[3];
    const float* Wv  = (const float*)d_in[4];
    const float* Wo  = (const float*)d_in[5];
    const float* cq  = (const float*)d_in[6];
    const float* sq  = (const float*)d_in[7];
    const float* ck  = (const float*)d_in[8];
    const float* sk  = (const float*)d_in[9];

    __half *hs_c, *enc_c, *wq_c, *wk_c, *wv_c, *wo_c;
    __half *q_c, *k_c, *v_c, *c_c;
    cudaGetSymbolAddress((void**)&hs_c,  g_hs);
    cudaGetSymbolAddress((void**)&enc_c, g_enc);
    cudaGetSymbolAddress((void**)&wq_c,  g_wq);
    cudaGetSymbolAddress((void**)&wk_c,  g_wk);
    cudaGetSymbolAddress((void**)&wv_c,  g_wv);
    cudaGetSymbolAddress((void**)&wo_c,  g_wo);
    cudaGetSymbolAddress((void**)&q_c, g_q);
    cudaGetSymbolAddress((void**)&k_c, g_k);
    cudaGetSymbolAddress((void**)&v_c, g_v);
    cudaGetSymbolAddress((void**)&c_c, g_c);

    {
        const size_t nthreads = CONV_TOT / 4;
        conv_all<<<(unsigned)((nthreads + 255) / 256), 256>>>(
            hs, enc, Wq, Wk, Wv, Wo, hs_c, enc_c, wq_c, wk_c, wv_c, wo_c);
    }

    cudaFuncSetAttribute(gemm_kernel<true>,
                         cudaFuncAttributeMaxDynamicSharedMemorySize, SMEM_GEMM);
    cudaFuncSetAttribute(gemm_kernel<false>,
                         cudaFuncAttributeMaxDynamicSharedMemorySize, SMEM_GEMM);
    cudaFuncSetAttribute(attn_kernel,
                         cudaFuncAttributeMaxDynamicSharedMemorySize, ATT_SMEM);

    // Q/K/V projections (+RoPE, +head split, +V transpose)
    gemm_kernel<true><<<dim3(DD / 128, MM / 128, 3), GTHREADS, SMEM_GEMM>>>(
        hs_c, enc_c, wq_c, wk_c, wv_c,
        cq, sq, ck, sk, q_c, k_c, v_c, nullptr);

    // Attention
    attn_kernel<<<dim3(TT / 128, BB * HH), 256, ATT_SMEM>>>(
        q_c, k_c, v_c, c_c);

    // Output projection (fp32 out)
    gemm_kernel<false><<<dim3(DD / 128, MM / 128, 1), GTHREADS, SMEM_GEMM>>>(
        c_c, nullptr, wo_c, nullptr, nullptr,
        nullptr, nullptr, nullptr, nullptr,
        nullptr, nullptr, nullptr, (float*)d_out);
}

// round 11
// speedup vs baseline: 2.5818x; 1.0608x over previous
#include <cuda_runtime.h>
#include <cuda_fp16.h>
#include <cstdint>
#include <cstddef>
#include <math.h>

// ---------------------------------------------------------------------------
#define BB 2
#define HH 16
#define TT 2048
#define DD 2048
#define HD 128
#define KK 2048
#define MM 4096
#define SCALE 0.08838834764831845f
#define CH (BB * HH * TT * HD)

// ---------------------------------------------------------------------------
// Scratch (device globals; allocation is forbidden).  All single fp16.
// ---------------------------------------------------------------------------
__device__ __half g_hs[MM * KK];
__device__ __half g_enc[MM * KK];
__device__ __half g_wq[DD * KK];
__device__ __half g_wk[DD * KK];
__device__ __half g_wv[DD * KK];
__device__ __half g_wo[DD * KK];
__device__ __half g_q[CH];                  // [B,H,T,HD]
__device__ __half g_k[CH];                  // [B,H,S,HD]
__device__ __half g_v[CH];                  // [B,H,HD,S] transposed
__device__ __half g_c[MM * DD];             // ctx [B,T,D]

// ---------------------------------------------------------------------------
// Helpers (baseline sm_80 features only)
// ---------------------------------------------------------------------------
__device__ __forceinline__ uint32_t smem_to_u32(const void* p) {
    uint32_t a;
    asm("{ .reg .u64 t; cvta.to.shared.u64 t, %1; cvt.u32.u64 %0, t; }" : "=r"(a) : "l"(p));
    return a;
}
__device__ __forceinline__ void cp_async16(uint32_t dst, const void* src) {
    asm volatile("cp.async.cg.shared.global [%0], [%1], 16;" :: "r"(dst), "l"(src));
}
#define CP_ASYNC_COMMIT() asm volatile("cp.async.commit_group;" ::: "memory")
#define CP_ASYNC_WAIT(n)  asm volatile("cp.async.wait_group %0;" :: "n"(n) : "memory")

__device__ __forceinline__ void ldm4(uint32_t* r, uint32_t addr) {
    asm volatile("ldmatrix.sync.aligned.m8n8.x4.shared.b16 {%0,%1,%2,%3}, [%4];"
                 : "=r"(r[0]), "=r"(r[1]), "=r"(r[2]), "=r"(r[3]) : "r"(addr));
}
__device__ __forceinline__ void mma16816(float* c, const uint32_t* a, uint32_t b0, uint32_t b1) {
    asm volatile("mma.sync.aligned.m16n8k16.row.col.f32.f16.f16.f32 "
                 "{%0,%1,%2,%3}, {%4,%5,%6,%7}, {%8,%9}, {%0,%1,%2,%3};"
                 : "+f"(c[0]), "+f"(c[1]), "+f"(c[2]), "+f"(c[3])
                 : "r"(a[0]), "r"(a[1]), "r"(a[2]), "r"(a[3]), "r"(b0), "r"(b1));
}
__device__ __forceinline__ uint32_t packhf(__half a, __half b) {
    __half2 t(a, b);
    return *reinterpret_cast<uint32_t*>(&t);
}

// ---------------------------------------------------------------------------
// Fused fp32 -> fp16 convert for all 6 input tensors
// ---------------------------------------------------------------------------
#define NAE ((size_t)MM * KK)
#define NWE ((size_t)DD * KK)
#define CONV_TOT ((2 * NAE + 4 * NWE) / 4)   // in float4 units

__global__ __launch_bounds__(256)
void conv_all(const float* __restrict__ hs, const float* __restrict__ enc,
              const float* __restrict__ wq, const float* __restrict__ wk,
              const float* __restrict__ wv, const float* __restrict__ wo,
              __half* __restrict__ hs_o, __half* __restrict__ enc_o,
              __half* __restrict__ wq_o, __half* __restrict__ wk_o,
              __half* __restrict__ wv_o, __half* __restrict__ wo_o)
{
    size_t i = ((size_t)blockIdx.x * 256 + threadIdx.x) * 4;   // first float4
    if (i >= CONV_TOT) return;
    const size_t A4 = NAE / 4, W4 = NWE / 4;
    const float* src; __half* dst; size_t base;
    if      (i < A4)            { src = hs;  dst = hs_o;  base = 0; }
    else if (i < 2 * A4)        { src = enc; dst = enc_o; base = A4; }
    else if (i < 2 * A4 + W4)   { src = wq;  dst = wq_o;  base = 2 * A4; }
    else if (i < 2 * A4 + 2 * W4) { src = wk; dst = wk_o; base = 2 * A4 + W4; }
    else if (i < 2 * A4 + 3 * W4) { src = wv; dst = wv_o; base = 2 * A4 + 2 * W4; }
    else                        { src = wo;  dst = wo_o;  base = 2 * A4 + 3 * W4; }
    const size_t j = i - base;
    #pragma unroll
    for (int u = 0; u < 4; ++u) {
        float4 v = ((const float4*)src)[j + u];
        ((uint32_t*)dst)[2 * (j + u)]     = packhf(__float2half(v.x), __float2half(v.y));
        ((uint32_t*)dst)[2 * (j + u) + 1] = packhf(__float2half(v.z), __float2half(v.w));
    }
}

// ---------------------------------------------------------------------------
// 1-pass fp16 GEMM: out = A * W^T, fp32 accum.  128x128 CTA tile, BK=64
// (round-10 fix: halve the barrier count — per-stage sync overhead was the
// 17% gap vs the HMMA ceiling).  Row stride 144B (128 data + 16 pad,
// conflict-free: 16r mod 128 is a permutation per ldmatrix phase).
// 4 warps (64x64 warp tile), 3-stage ring (110.6KB), 2 CTAs/SM.
// ---------------------------------------------------------------------------
#define TILE_B 18432                   // 128 rows * 144B
#define STAGE_B (2 * TILE_B)           // A, W
#define SMEM_GEMM (3 * STAGE_B)        // 110592 -> 2 CTAs/SM
#define NSTAGES (KK / 64)              // 32
#define GTHREADS 128

__device__ __forceinline__ void load_stage_g(
    uint32_t sbuf, int s, int m0, int n0,
    const __half* __restrict__ A, const __half* __restrict__ W, int tid)
{
    const int k0 = s * 64;
    #pragma unroll
    for (int q = 0; q < 8; ++q) {
        const int id = tid + GTHREADS * q;      // 0..1023
        const int r = id >> 3, c = id & 7;      // 128 rows x 8 chunks of 16B
        const uint32_t doff = r * 144 + c * 16;
        const size_t gA = (size_t)(m0 + r) * KK + k0 + c * 8;
        const size_t gW = (size_t)(n0 + r) * KK + k0 + c * 8;
        cp_async16(sbuf + doff,          A + gA);
        cp_async16(sbuf + TILE_B + doff, W + gW);
    }
}

template<bool QKV>
__global__ __launch_bounds__(GTHREADS, 2)
void gemm_kernel(const __half* __restrict__ a0, const __half* __restrict__ a1,
                 const __half* __restrict__ w0, const __half* __restrict__ w1,
                 const __half* __restrict__ w2,
                 const float* __restrict__ cq, const float* __restrict__ sq,
                 const float* __restrict__ ck, const float* __restrict__ sk,
                 __half* __restrict__ qo, __half* __restrict__ ko,
                 __half* __restrict__ vo,
                 float* __restrict__ fout)
{
    extern __shared__ __align__(128) uint8_t smem_raw[];
    const uint32_t sbase = smem_to_u32(smem_raw);
    const int tid = threadIdx.x;
    const int m0 = blockIdx.y * 128;
    const int n0 = blockIdx.x * 128;
    const int z  = QKV ? blockIdx.z : 0;

    const __half *A, *W;
    if (QKV) {
        A = (z == 0) ? a0 : a1;
        W = (z == 0) ? w0 : (z == 1) ? w1 : w2;
    } else {
        A = a0; W = w0;
    }

    const int wid = tid >> 5, lid = tid & 31;
    const int wm = wid >> 1, wn = wid & 1;
    const int g = lid >> 2, t = lid & 3;
    const int lrow = lid & 15;
    const int lcolb = (lid >> 4) * 16;

    float acc[4][8][4];
    #pragma unroll
    for (int mt = 0; mt < 4; ++mt)
        #pragma unroll
        for (int nt = 0; nt < 8; ++nt)
            #pragma unroll
            for (int q = 0; q < 4; ++q) acc[mt][nt][q] = 0.0f;

    load_stage_g(sbase, 0, m0, n0, A, W, tid); CP_ASYNC_COMMIT();
    load_stage_g(sbase + STAGE_B, 1, m0, n0, A, W, tid); CP_ASYNC_COMMIT();

    for (int s = 0; s < NSTAGES; ++s) {
        CP_ASYNC_WAIT(1);
        __syncthreads();
        // 3 distinct ring slots: computing s%3, pending (s+1)%3, loading (s+2)%3
        if (s + 2 < NSTAGES) {
            int bslot = s + 2 - ((s + 2) / 3) * 3;
            load_stage_g(sbase + bslot * STAGE_B, s + 2, m0, n0, A, W, tid);
        }
        CP_ASYNC_COMMIT();

        const uint32_t buf = sbase + (s % 3) * STAGE_B;
        const uint32_t aT = buf, bT = buf + TILE_B;

        #pragma unroll
        for (int kc = 0; kc < 4; ++kc) {        // 4 k16 steps in BK=64
            const uint32_t cb = kc * 32 + lcolb;
            uint32_t af[4][4], bf[4][4];
            #pragma unroll
            for (int mt = 0; mt < 4; ++mt)
                ldm4(af[mt], aT + (wm * 64 + mt * 16 + lrow) * 144 + cb);
            #pragma unroll
            for (int jp = 0; jp < 4; ++jp)
                ldm4(bf[jp], bT + (wn * 64 + jp * 16 + lrow) * 144 + cb);
            #pragma unroll
            for (int jp = 0; jp < 4; ++jp)
                #pragma unroll
                for (int mt = 0; mt < 4; ++mt) {
                    mma16816(acc[mt][2 * jp],     af[mt], bf[jp][0], bf[jp][2]);
                    mma16816(acc[mt][2 * jp + 1], af[mt], bf[jp][1], bf[jp][3]);
                }
        }
    }

    // ---------------- epilogue ----------------
    #pragma unroll
    for (int mt = 0; mt < 4; ++mt) {
        #pragma unroll
        for (int rh = 0; rh < 2; ++rh) {
            const int m = m0 + wm * 64 + mt * 16 + g + rh * 8;
            const int tI = m & (TT - 1);
            const int b  = m >> 11;
            #pragma unroll
            for (int nt = 0; nt < 8; ++nt) {
                const int col = wn * 64 + nt * 8 + 2 * t;
                float v0 = acc[mt][nt][rh * 2 + 0];
                float v1 = acc[mt][nt][rh * 2 + 1];
                if (QKV) {
                    if (z < 2) {
                        const float* cT = (z == 0) ? cq : ck;
                        const float* sT = (z == 0) ? sq : sk;
                        const int d2 = col >> 1;
                        const float cs = cT[tI * 64 + d2];
                        const float sn = sT[tI * 64 + d2];
                        const float x0 = v0, x1 = v1;
                        v0 = x0 * cs - x1 * sn;
                        v1 = x1 * cs + x0 * sn;
                    }
                    const int hhead = blockIdx.x;
                    const size_t bh = (size_t)b * HH + hhead;
                    if (z == 2) {
                        const size_t base = (bh * HD + col) * TT + tI;
                        vo[base]      = __float2half(v0);
                        vo[base + TT] = __float2half(v1);
                    } else {
                        const size_t off = (bh * TT + tI) * HD + col;
                        __half* op = (z == 0) ? qo : ko;
                        *(uint32_t*)(op + off) = packhf(__float2half(v0), __float2half(v1));
                    }
                } else {
                    float* op = fout + (size_t)m * DD + n0 + col;
                    *(float2*)op = make_float2(v0, v1);
                }
            }
        }
    }
}

// ---------------------------------------------------------------------------
// Flash attention (unchanged from round 10 — measured at the HMMA ceiling)
// ---------------------------------------------------------------------------
#define AQ_STR 272
#define AV_STR 144
#define OFF_KV 34816                 // 128*272 (Q)
#define OFF_VH 17408                 // within buf: after K
#define KV_BUF 35840                 // 17408 + 18432
#define ATT_SMEM (OFF_KV + 2 * KV_BUF)   // 106496

__device__ __forceinline__ void load_kv_chunk(
    uint32_t sb, int buf, int chunk, int bh,
    const __half* __restrict__ k_g, const __half* __restrict__ v_g, int tid)
{
    const uint32_t kb = sb + OFF_KV + buf * KV_BUF;
    const int s0 = chunk * 64;
    #pragma unroll
    for (int i = 0; i < 4; ++i) {
        const int idx = tid + 256 * i;
        const int r = idx >> 4, c2 = idx & 15;  // K: 64 rows x 16 chunks
        const size_t gk = ((size_t)bh * TT + s0 + r) * HD + c2 * 8;
        cp_async16(kb + r * AQ_STR + c2 * 16, k_g + gk);
        const int rv = idx >> 3, cv = idx & 7;  // Vt: 128 rows x 8 chunks
        const size_t gv = ((size_t)bh * HD + rv) * TT + s0 + cv * 8;
        cp_async16(kb + OFF_VH + rv * AV_STR + cv * 16, v_g + gv);
    }
}

__global__ __launch_bounds__(256, 1)
void attn_kernel(const __half* __restrict__ q_g, const __half* __restrict__ k_g,
                 const __half* __restrict__ v_g, __half* __restrict__ c_g)
{
    extern __shared__ __align__(128) uint8_t sm_raw[];
    const uint32_t sb = smem_to_u32(sm_raw);
    const int tid = threadIdx.x;
    const int wid = tid >> 5, lid = tid & 31;
    const int g = lid >> 2, t = lid & 3;
    const int bh = blockIdx.y;
    const int b = bh >> 4, h = bh & 15;
    const int q0 = blockIdx.x * 128;
    const int lrow = lid & 15;
    const int lcolb = (lid >> 4) * 16;

    const size_t qoff = ((size_t)bh * TT + q0) * HD;
    #pragma unroll
    for (int i = 0; i < 4; ++i) {
        const int idx = tid + 256 * i;          // 0..1023
        const int r = idx >> 3, c2 = idx & 7;   // 128 rows x 8 chunks of 16B
        const size_t gq = qoff + (size_t)r * HD + c2 * 16;
        cp_async16(sb + r * AQ_STR + c2 * 32,      q_g + gq);
        cp_async16(sb + r * AQ_STR + c2 * 32 + 16, q_g + gq + 8);
    }
    load_kv_chunk(sb, 0, 0, bh, k_g, v_g, tid);
    CP_ASYNC_COMMIT();
    load_kv_chunk(sb, 1, 1, bh, k_g, v_g, tid);
    CP_ASYNC_COMMIT();

    float O[16][4];
    #pragma unroll
    for (int nv = 0; nv < 16; ++nv)
        #pragma unroll
        for (int q = 0; q < 4; ++q) O[nv][q] = 0.0f;
    float mr0 = -1e30f, mr1 = -1e30f, lr0 = 0.0f, lr1 = 0.0f;

    for (int c = 0; c < 32; ++c) {
        CP_ASYNC_WAIT(1);
        __syncthreads();
        const uint32_t kb = sb + OFF_KV + (c & 1) * KV_BUF;

        // ---- S = Q K^T (1-pass fp16) ----
        float S[8][4];
        #pragma unroll
        for (int j = 0; j < 8; ++j)
            #pragma unroll
            for (int q = 0; q < 4; ++q) S[j][q] = 0.0f;

        #pragma unroll
        for (int ks = 0; ks < 8; ++ks) {
            const uint32_t cb = ks * 32 + lcolb;
            uint32_t qf[4], kf[4][4];
            ldm4(qf, sb + (wid * 16 + lrow) * AQ_STR + cb);
            #pragma unroll
            for (int jp = 0; jp < 4; ++jp)
                ldm4(kf[jp], kb + (jp * 16 + lrow) * AQ_STR + cb);
            #pragma unroll
            for (int jp = 0; jp < 4; ++jp) {
                mma16816(S[2 * jp],     qf, kf[jp][0], kf[jp][2]);
                mma16816(S[2 * jp + 1], qf, kf[jp][1], kf[jp][3]);
            }
        }

        // ---- online softmax (fp32) ----
        float mx0 = -1e30f, mx1 = -1e30f;
        #pragma unroll
        for (int j = 0; j < 8; ++j) {
            #pragma unroll
            for (int q = 0; q < 4; ++q) S[j][q] *= SCALE;
            mx0 = fmaxf(mx0, fmaxf(S[j][0], S[j][1]));
            mx1 = fmaxf(mx1, fmaxf(S[j][2], S[j][3]));
        }
        mx0 = fmaxf(mx0, __shfl_xor_sync(0xffffffffu, mx0, 1));
        mx0 = fmaxf(mx0, __shfl_xor_sync(0xffffffffu, mx0, 2));
        mx1 = fmaxf(mx1, __shfl_xor_sync(0xffffffffu, mx1, 1));
        mx1 = fmaxf(mx1, __shfl_xor_sync(0xffffffffu, mx1, 2));
        const float mn0 = fmaxf(mr0, mx0), mn1 = fmaxf(mr1, mx1);
        const float cr0 = __expf(mr0 - mn0), cr1 = __expf(mr1 - mn1);
        mr0 = mn0; mr1 = mn1;
        float ls0 = 0.0f, ls1 = 0.0f;
        #pragma unroll
        for (int j = 0; j < 8; ++j) {
            S[j][0] = __expf(S[j][0] - mn0);
            S[j][1] = __expf(S[j][1] - mn0);
            S[j][2] = __expf(S[j][2] - mn1);
            S[j][3] = __expf(S[j][3] - mn1);
            ls0 += S[j][0] + S[j][1];
            ls1 += S[j][2] + S[j][3];
        }
        ls0 += __shfl_xor_sync(0xffffffffu, ls0, 1);
        ls0 += __shfl_xor_sync(0xffffffffu, ls0, 2);
        ls1 += __shfl_xor_sync(0xffffffffu, ls1, 1);
        ls1 += __shfl_xor_sync(0xffffffffu, ls1, 2);
        lr0 = lr0 * cr0 + ls0;
        lr1 = lr1 * cr1 + ls1;
        #pragma unroll
        for (int nv = 0; nv < 16; ++nv) {
            O[nv][0] *= cr0; O[nv][1] *= cr0;
            O[nv][2] *= cr1; O[nv][3] *= cr1;
        }

        // ---- P fragments (single fp16) ----
        uint32_t pf[4][4];
        #pragma unroll
        for (int kk = 0; kk < 4; ++kk) {
            pf[kk][0] = packhf(__float2half(S[2 * kk][0]),     __float2half(S[2 * kk][1]));
            pf[kk][1] = packhf(__float2half(S[2 * kk][2]),     __float2half(S[2 * kk][3]));
            pf[kk][2] = packhf(__float2half(S[2 * kk + 1][0]), __float2half(S[2 * kk + 1][1]));
            pf[kk][3] = packhf(__float2half(S[2 * kk + 1][2]), __float2half(S[2 * kk + 1][3]));
        }

        // ---- O += P V (1-pass) ----
        const uint32_t vb = kb + OFF_VH;
        #pragma unroll
        for (int kk = 0; kk < 4; ++kk) {
            const uint32_t cb = kk * 32 + lcolb;
            #pragma unroll
            for (int half = 0; half < 2; ++half) {
                uint32_t vf[4][4];
                #pragma unroll
                for (int u = 0; u < 4; ++u)
                    ldm4(vf[u], vb + ((half * 4 + u) * 16 + lrow) * AV_STR + cb);
                #pragma unroll
                for (int u = 0; u < 4; ++u) {
                    const int np = half * 4 + u;
                    mma16816(O[2 * np],     pf[kk], vf[u][0], vf[u][2]);
                    mma16816(O[2 * np + 1], pf[kk], vf[u][1], vf[u][3]);
                }
            }
        }

        __syncthreads();
        if (c + 2 < 32)
            load_kv_chunk(sb, c & 1, c + 2, bh, k_g, v_g, tid);
        CP_ASYNC_COMMIT();
    }

    // ---- epilogue: ctx single fp16 ----
    const float inv0 = 1.0f / lr0, inv1 = 1.0f / lr1;
    const int t0 = q0 + wid * 16 + g;
    const int t1 = t0 + 8;
    #pragma unroll
    for (int nv = 0; nv < 16; ++nv) {
        const int d = h * HD + nv * 8 + 2 * t;
        const size_t o0 = ((size_t)b * TT + t0) * DD + d;
        const size_t o1 = ((size_t)b * TT + t1) * DD + d;
        *(uint32_t*)(c_g + o0) =
            packhf(__float2half(O[nv][0] * inv0), __float2half(O[nv][1] * inv0));
        *(uint32_t*)(c_g + o1) =
            packhf(__float2half(O[nv][2] * inv1), __float2half(O[nv][3] * inv1));
    }
}

// ---------------------------------------------------------------------------
extern "C" void kernel_launch(void* const* d_in, const int* in_sizes, int n_in,
                              void* d_out, int out_size)
{
    const float* hs  = (const float*)d_in[0];
    const float* enc = (const float*)d_in[1];
    const float* Wq  = (const float*)d_in[2];
    const float* Wk  = (const float*)d_in[3];
    const float* Wv  = (const float*)d_in[4];
    const float* Wo  = (const float*)d_in[5];
    const float* cq  = (const float*)d_in[6];
    const float* sq  = (const float*)d_in[7];
    const float* ck  = (const float*)d_in[8];
    const float* sk  = (const float*)d_in[9];

    __half *hs_c, *enc_c, *wq_c, *wk_c, *wv_c, *wo_c;
    __half *q_c, *k_c, *v_c, *c_c;
    cudaGetSymbolAddress((void**)&hs_c,  g_hs);
    cudaGetSymbolAddress((void**)&enc_c, g_enc);
    cudaGetSymbolAddress((void**)&wq_c,  g_wq);
    cudaGetSymbolAddress((void**)&wk_c,  g_wk);
    cudaGetSymbolAddress((void**)&wv_c,  g_wv);
    cudaGetSymbolAddress((void**)&wo_c,  g_wo);
    cudaGetSymbolAddress((void**)&q_c, g_q);
    cudaGetSymbolAddress((void**)&k_c, g_k);
    cudaGetSymbolAddress((void**)&v_c, g_v);
    cudaGetSymbolAddress((void**)&c_c, g_c);

    {
        const size_t nthreads = CONV_TOT / 4;
        conv_all<<<(unsigned)((nthreads + 255) / 256), 256>>>(
            hs, enc, Wq, Wk, Wv, Wo, hs_c, enc_c, wq_c, wk_c, wv_c, wo_c);
    }

    cudaFuncSetAttribute(gemm_kernel<true>,
                         cudaFuncAttributeMaxDynamicSharedMemorySize, SMEM_GEMM);
    cudaFuncSetAttribute(gemm_kernel<false>,
                         cudaFuncAttributeMaxDynamicSharedMemorySize, SMEM_GEMM);
    cudaFuncSetAttribute(attn_kernel,
                         cudaFuncAttributeMaxDynamicSharedMemorySize, ATT_SMEM);

    // Q/K/V projections (+RoPE, +head split, +V transpose)
    gemm_kernel<true><<<dim3(DD / 128, MM / 128, 3), GTHREADS, SMEM_GEMM>>>(
        hs_c, enc_c, wq_c, wk_c, wv_c,
        cq, sq, ck, sk, q_c, k_c, v_c, nullptr);

    // Attention
    attn_kernel<<<dim3(TT / 128, BB * HH), 256, ATT_SMEM>>>(
        q_c, k_c, v_c, c_c);

    // Output projection (fp32 out)
    gemm_kernel<false><<<dim3(DD / 128, MM / 128, 1), GTHREADS, SMEM_GEMM>>>(
        c_c, nullptr, wo_c, nullptr, nullptr,
        nullptr, nullptr, nullptr, nullptr,
        nullptr, nullptr, nullptr, (float*)d_out);
}

// round 12
// speedup vs baseline: 2.7318x; 1.0581x over previous
#include <cuda_runtime.h>
#include <cuda_fp16.h>
#include <cstdint>
#include <cstddef>
#include <math.h>

// ---------------------------------------------------------------------------
#define BB 2
#define HH 16
#define TT 2048
#define DD 2048
#define HD 128
#define KK 2048
#define MM 4096
#define SCALE 0.08838834764831845f
#define CH (BB * HH * TT * HD)

// ---------------------------------------------------------------------------
// Scratch (device globals; allocation is forbidden).  All single fp16.
// ---------------------------------------------------------------------------
__device__ __half g_hs[MM * KK];
__device__ __half g_enc[MM * KK];
__device__ __half g_wq[DD * KK];
__device__ __half g_wk[DD * KK];
__device__ __half g_wv[DD * KK];
__device__ __half g_wo[DD * KK];
__device__ __half g_q[CH];                  // [B,H,T,HD]
__device__ __half g_k[CH];                  // [B,H,S,HD]
__device__ __half g_v[CH];                  // [B,H,HD,S] transposed
__device__ __half g_c[MM * DD];             // ctx [B,T,D]

// ---------------------------------------------------------------------------
// Helpers (baseline sm_80 features only)
// ---------------------------------------------------------------------------
__device__ __forceinline__ uint32_t smem_to_u32(const void* p) {
    uint32_t a;
    asm("{ .reg .u64 t; cvta.to.shared.u64 t, %1; cvt.u32.u64 %0, t; }" : "=r"(a) : "l"(p));
    return a;
}
__device__ __forceinline__ void cp_async16(uint32_t dst, const void* src) {
    asm volatile("cp.async.cg.shared.global [%0], [%1], 16;" :: "r"(dst), "l"(src));
}
#define CP_ASYNC_COMMIT() asm volatile("cp.async.commit_group;" ::: "memory")
#define CP_ASYNC_WAIT(n)  asm volatile("cp.async.wait_group %0;" :: "n"(n) : "memory")

__device__ __forceinline__ void ldm4(uint32_t* r, uint32_t addr) {
    asm volatile("ldmatrix.sync.aligned.m8n8.x4.shared.b16 {%0,%1,%2,%3}, [%4];"
                 : "=r"(r[0]), "=r"(r[1]), "=r"(r[2]), "=r"(r[3]) : "r"(addr));
}
__device__ __forceinline__ void mma16816(float* c, const uint32_t* a, uint32_t b0, uint32_t b1) {
    asm volatile("mma.sync.aligned.m16n8k16.row.col.f32.f16.f16.f32 "
                 "{%0,%1,%2,%3}, {%4,%5,%6,%7}, {%8,%9}, {%0,%1,%2,%3};"
                 : "+f"(c[0]), "+f"(c[1]), "+f"(c[2]), "+f"(c[3])
                 : "r"(a[0]), "r"(a[1]), "r"(a[2]), "r"(a[3]), "r"(b0), "r"(b1));
}
__device__ __forceinline__ uint32_t packhf(__half a, __half b) {
    __half2 t(a, b);
    return *reinterpret_cast<uint32_t*>(&t);
}

// ---------------------------------------------------------------------------
// Fused fp32 -> fp16 convert, 32 elements/thread (8x LDG.128, 4x STG.128)
// ---------------------------------------------------------------------------
#define NAE ((size_t)MM * KK)
#define NWE ((size_t)DD * KK)
#define TOT_E (2 * NAE + 4 * NWE)            // 32M elements

__global__ __launch_bounds__(256)
void conv_all(const float* __restrict__ hs, const float* __restrict__ enc,
              const float* __restrict__ wq, const float* __restrict__ wk,
              const float* __restrict__ wv, const float* __restrict__ wo,
              __half* __restrict__ hs_o, __half* __restrict__ enc_o,
              __half* __restrict__ wq_o, __half* __restrict__ wk_o,
              __half* __restrict__ wv_o, __half* __restrict__ wo_o)
{
    size_t e = ((size_t)blockIdx.x * 256 + threadIdx.x) * 32;
    if (e >= TOT_E) return;
    const float* src; __half* dst; size_t base;
    if      (e < NAE)            { src = hs;  dst = hs_o;  base = 0; }
    else if (e < 2 * NAE)        { src = enc; dst = enc_o; base = NAE; }
    else if (e < 2 * NAE + NWE)  { src = wq;  dst = wq_o;  base = 2 * NAE; }
    else if (e < 2 * NAE + 2 * NWE) { src = wk; dst = wk_o; base = 2 * NAE + NWE; }
    else if (e < 2 * NAE + 3 * NWE) { src = wv; dst = wv_o; base = 2 * NAE + 2 * NWE; }
    else                         { src = wo;  dst = wo_o;  base = 2 * NAE + 3 * NWE; }
    const size_t j = e - base;
    const float4* s4 = (const float4*)src + (j >> 2);
    uint4* d4 = (uint4*)dst + (j >> 3);
    #pragma unroll
    for (int v = 0; v < 4; ++v) {
        float4 a = s4[2 * v];
        float4 b = s4[2 * v + 1];
        uint4 o;
        o.x = packhf(__float2half(a.x), __float2half(a.y));
        o.y = packhf(__float2half(a.z), __float2half(a.w));
        o.z = packhf(__float2half(b.x), __float2half(b.y));
        o.w = packhf(__float2half(b.z), __float2half(b.w));
        d4[v] = o;
    }
}

// ---------------------------------------------------------------------------
// 1-pass fp16 GEMM (unchanged from round 11: 128x128 CTA tile, BK=64,
// 4 warps 64x64, 3-stage ring, 2 CTAs/SM — measured 91% of HMMA ceiling)
// ---------------------------------------------------------------------------
#define TILE_B 18432                   // 128 rows * 144B
#define STAGE_B (2 * TILE_B)
#define SMEM_GEMM (3 * STAGE_B)        // 110592 -> 2 CTAs/SM
#define NSTAGES (KK / 64)              // 32
#define GTHREADS 128

__device__ __forceinline__ void load_stage_g(
    uint32_t sbuf, int s, int m0, int n0,
    const __half* __restrict__ A, const __half* __restrict__ W, int tid)
{
    const int k0 = s * 64;
    #pragma unroll
    for (int q = 0; q < 8; ++q) {
        const int id = tid + GTHREADS * q;      // 0..1023
        const int r = id >> 3, c = id & 7;
        const uint32_t doff = r * 144 + c * 16;
        const size_t gA = (size_t)(m0 + r) * KK + k0 + c * 8;
        const size_t gW = (size_t)(n0 + r) * KK + k0 + c * 8;
        cp_async16(sbuf + doff,          A + gA);
        cp_async16(sbuf + TILE_B + doff, W + gW);
    }
}

template<bool QKV>
__global__ __launch_bounds__(GTHREADS, 2)
void gemm_kernel(const __half* __restrict__ a0, const __half* __restrict__ a1,
                 const __half* __restrict__ w0, const __half* __restrict__ w1,
                 const __half* __restrict__ w2,
                 const float* __restrict__ cq, const float* __restrict__ sq,
                 const float* __restrict__ ck, const float* __restrict__ sk,
                 __half* __restrict__ qo, __half* __restrict__ ko,
                 __half* __restrict__ vo,
                 float* __restrict__ fout)
{
    extern __shared__ __align__(128) uint8_t smem_raw[];
    const uint32_t sbase = smem_to_u32(smem_raw);
    const int tid = threadIdx.x;
    const int m0 = blockIdx.y * 128;
    const int n0 = blockIdx.x * 128;
    const int z  = QKV ? blockIdx.z : 0;

    const __half *A, *W;
    if (QKV) {
        A = (z == 0) ? a0 : a1;
        W = (z == 0) ? w0 : (z == 1) ? w1 : w2;
    } else {
        A = a0; W = w0;
    }

    const int wid = tid >> 5, lid = tid & 31;
    const int wm = wid >> 1, wn = wid & 1;
    const int g = lid >> 2, t = lid & 3;
    const int lrow = lid & 15;
    const int lcolb = (lid >> 4) * 16;

    float acc[4][8][4];
    #pragma unroll
    for (int mt = 0; mt < 4; ++mt)
        #pragma unroll
        for (int nt = 0; nt < 8; ++nt)
            #pragma unroll
            for (int q = 0; q < 4; ++q) acc[mt][nt][q] = 0.0f;

    load_stage_g(sbase, 0, m0, n0, A, W, tid); CP_ASYNC_COMMIT();
    load_stage_g(sbase + STAGE_B, 1, m0, n0, A, W, tid); CP_ASYNC_COMMIT();

    for (int s = 0; s < NSTAGES; ++s) {
        CP_ASYNC_WAIT(1);
        __syncthreads();
        if (s + 2 < NSTAGES) {
            int bslot = s + 2 - ((s + 2) / 3) * 3;
            load_stage_g(sbase + bslot * STAGE_B, s + 2, m0, n0, A, W, tid);
        }
        CP_ASYNC_COMMIT();

        const uint32_t buf = sbase + (s % 3) * STAGE_B;
        const uint32_t aT = buf, bT = buf + TILE_B;

        #pragma unroll
        for (int kc = 0; kc < 4; ++kc) {
            const uint32_t cb = kc * 32 + lcolb;
            uint32_t af[4][4], bf[4][4];
            #pragma unroll
            for (int mt = 0; mt < 4; ++mt)
                ldm4(af[mt], aT + (wm * 64 + mt * 16 + lrow) * 144 + cb);
            #pragma unroll
            for (int jp = 0; jp < 4; ++jp)
                ldm4(bf[jp], bT + (wn * 64 + jp * 16 + lrow) * 144 + cb);
            #pragma unroll
            for (int jp = 0; jp < 4; ++jp)
                #pragma unroll
                for (int mt = 0; mt < 4; ++mt) {
                    mma16816(acc[mt][2 * jp],     af[mt], bf[jp][0], bf[jp][2]);
                    mma16816(acc[mt][2 * jp + 1], af[mt], bf[jp][1], bf[jp][3]);
                }
        }
    }

    // ---------------- epilogue ----------------
    #pragma unroll
    for (int mt = 0; mt < 4; ++mt) {
        #pragma unroll
        for (int rh = 0; rh < 2; ++rh) {
            const int m = m0 + wm * 64 + mt * 16 + g + rh * 8;
            const int tI = m & (TT - 1);
            const int b  = m >> 11;
            #pragma unroll
            for (int nt = 0; nt < 8; ++nt) {
                const int col = wn * 64 + nt * 8 + 2 * t;
                float v0 = acc[mt][nt][rh * 2 + 0];
                float v1 = acc[mt][nt][rh * 2 + 1];
                if (QKV) {
                    if (z < 2) {
                        const float* cT = (z == 0) ? cq : ck;
                        const float* sT = (z == 0) ? sq : sk;
                        const int d2 = col >> 1;
                        const float cs = cT[tI * 64 + d2];
                        const float sn = sT[tI * 64 + d2];
                        const float x0 = v0, x1 = v1;
                        v0 = x0 * cs - x1 * sn;
                        v1 = x1 * cs + x0 * sn;
                    }
                    const int hhead = blockIdx.x;
                    const size_t bh = (size_t)b * HH + hhead;
                    if (z == 2) {
                        const size_t base = (bh * HD + col) * TT + tI;
                        vo[base]      = __float2half(v0);
                        vo[base + TT] = __float2half(v1);
                    } else {
                        const size_t off = (bh * TT + tI) * HD + col;
                        __half* op = (z == 0) ? qo : ko;
                        *(uint32_t*)(op + off) = packhf(__float2half(v0), __float2half(v1));
                    }
                } else {
                    float* op = fout + (size_t)m * DD + n0 + col;
                    *(float2*)op = make_float2(v0, v1);
                }
            }
        }
    }
}

// ---------------------------------------------------------------------------
// Flash attention: BR=64, 128 threads (4 warps x 16 rows), 2 CTAs/SM.
// Round-11 change: co-resident CTA overlaps softmax with the other's MMA.
// smem: Q 64x272B; per buf: K 64x272B + Vt 128x144B. Dbl-buffered.
// ---------------------------------------------------------------------------
#define AQ_STR 272
#define AV_STR 144
#define OFF_KV 17408                 // 64*272 (Q)
#define OFF_VH 17408                 // within buf: after K
#define KV_BUF 35840                 // 17408 + 18432
#define ATT_SMEM (OFF_KV + 2 * KV_BUF)   // 89088 -> 2 CTAs/SM
#define ATHREADS 128

__device__ __forceinline__ void load_kv_chunk(
    uint32_t sb, int buf, int chunk, int bh,
    const __half* __restrict__ k_g, const __half* __restrict__ v_g, int tid)
{
    const uint32_t kb = sb + OFF_KV + buf * KV_BUF;
    const int s0 = chunk * 64;
    #pragma unroll
    for (int i = 0; i < 8; ++i) {
        const int idx = tid + ATHREADS * i;     // 0..1023
        const int r = idx >> 4, c2 = idx & 15;  // K: 64 rows x 16 chunks
        const size_t gk = ((size_t)bh * TT + s0 + r) * HD + c2 * 8;
        cp_async16(kb + r * AQ_STR + c2 * 16, k_g + gk);
        const int rv = idx >> 3, cv = idx & 7;  // Vt: 128 rows x 8 chunks
        const size_t gv = ((size_t)bh * HD + rv) * TT + s0 + cv * 8;
        cp_async16(kb + OFF_VH + rv * AV_STR + cv * 16, v_g + gv);
    }
}

__global__ __launch_bounds__(ATHREADS, 2)
void attn_kernel(const __half* __restrict__ q_g, const __half* __restrict__ k_g,
                 const __half* __restrict__ v_g, __half* __restrict__ c_g)
{
    extern __shared__ __align__(128) uint8_t sm_raw[];
    const uint32_t sb = smem_to_u32(sm_raw);
    const int tid = threadIdx.x;
    const int wid = tid >> 5, lid = tid & 31;
    const int g = lid >> 2, t = lid & 3;
    const int bh = blockIdx.y;
    const int b = bh >> 4, h = bh & 15;
    const int q0 = blockIdx.x * 64;
    const int lrow = lid & 15;
    const int lcolb = (lid >> 4) * 16;

    // Q tile: 64 rows x 256B
    const size_t qoff = ((size_t)bh * TT + q0) * HD;
    #pragma unroll
    for (int i = 0; i < 4; ++i) {
        const int idx = tid + ATHREADS * i;     // 0..511
        const int r = idx >> 3, c2 = idx & 7;   // 64 rows x 8 chunks of 32B
        const size_t gq = qoff + (size_t)r * HD + c2 * 16;
        cp_async16(sb + r * AQ_STR + c2 * 32,      q_g + gq);
        cp_async16(sb + r * AQ_STR + c2 * 32 + 16, q_g + gq + 8);
    }
    load_kv_chunk(sb, 0, 0, bh, k_g, v_g, tid);
    CP_ASYNC_COMMIT();
    load_kv_chunk(sb, 1, 1, bh, k_g, v_g, tid);
    CP_ASYNC_COMMIT();

    float O[16][4];
    #pragma unroll
    for (int nv = 0; nv < 16; ++nv)
        #pragma unroll
        for (int q = 0; q < 4; ++q) O[nv][q] = 0.0f;
    float mr0 = -1e30f, mr1 = -1e30f, lr0 = 0.0f, lr1 = 0.0f;

    for (int c = 0; c < 32; ++c) {
        CP_ASYNC_WAIT(1);
        __syncthreads();
        const uint32_t kb = sb + OFF_KV + (c & 1) * KV_BUF;

        // ---- S = Q K^T (1-pass fp16): warp owns rows wid*16..+15 ----
        float S[8][4];
        #pragma unroll
        for (int j = 0; j < 8; ++j)
            #pragma unroll
            for (int q = 0; q < 4; ++q) S[j][q] = 0.0f;

        #pragma unroll
        for (int ks = 0; ks < 8; ++ks) {
            const uint32_t cb = ks * 32 + lcolb;
            uint32_t qf[4], kf[4][4];
            ldm4(qf, sb + (wid * 16 + lrow) * AQ_STR + cb);
            #pragma unroll
            for (int jp = 0; jp < 4; ++jp)
                ldm4(kf[jp], kb + (jp * 16 + lrow) * AQ_STR + cb);
            #pragma unroll
            for (int jp = 0; jp < 4; ++jp) {
                mma16816(S[2 * jp],     qf, kf[jp][0], kf[jp][2]);
                mma16816(S[2 * jp + 1], qf, kf[jp][1], kf[jp][3]);
            }
        }

        // ---- online softmax (fp32) ----
        float mx0 = -1e30f, mx1 = -1e30f;
        #pragma unroll
        for (int j = 0; j < 8; ++j) {
            #pragma unroll
            for (int q = 0; q < 4; ++q) S[j][q] *= SCALE;
            mx0 = fmaxf(mx0, fmaxf(S[j][0], S[j][1]));
            mx1 = fmaxf(mx1, fmaxf(S[j][2], S[j][3]));
        }
        mx0 = fmaxf(mx0, __shfl_xor_sync(0xffffffffu, mx0, 1));
        mx0 = fmaxf(mx0, __shfl_xor_sync(0xffffffffu, mx0, 2));
        mx1 = fmaxf(mx1, __shfl_xor_sync(0xffffffffu, mx1, 1));
        mx1 = fmaxf(mx1, __shfl_xor_sync(0xffffffffu, mx1, 2));
        const float mn0 = fmaxf(mr0, mx0), mn1 = fmaxf(mr1, mx1);
        const float cr0 = __expf(mr0 - mn0), cr1 = __expf(mr1 - mn1);
        mr0 = mn0; mr1 = mn1;
        float ls0 = 0.0f, ls1 = 0.0f;
        #pragma unroll
        for (int j = 0; j < 8; ++j) {
            S[j][0] = __expf(S[j][0] - mn0);
            S[j][1] = __expf(S[j][1] - mn0);
            S[j][2] = __expf(S[j][2] - mn1);
            S[j][3] = __expf(S[j][3] - mn1);
            ls0 += S[j][0] + S[j][1];
            ls1 += S[j][2] + S[j][3];
        }
        ls0 += __shfl_xor_sync(0xffffffffu, ls0, 1);
        ls0 += __shfl_xor_sync(0xffffffffu, ls0, 2);
        ls1 += __shfl_xor_sync(0xffffffffu, ls1, 1);
        ls1 += __shfl_xor_sync(0xffffffffu, ls1, 2);
        lr0 = lr0 * cr0 + ls0;
        lr1 = lr1 * cr1 + ls1;
        #pragma unroll
        for (int nv = 0; nv < 16; ++nv) {
            O[nv][0] *= cr0; O[nv][1] *= cr0;
            O[nv][2] *= cr1; O[nv][3] *= cr1;
        }

        // ---- P fragments (single fp16) ----
        uint32_t pf[4][4];
        #pragma unroll
        for (int kk = 0; kk < 4; ++kk) {
            pf[kk][0] = packhf(__float2half(S[2 * kk][0]),     __float2half(S[2 * kk][1]));
            pf[kk][1] = packhf(__float2half(S[2 * kk][2]),     __float2half(S[2 * kk][3]));
            pf[kk][2] = packhf(__float2half(S[2 * kk + 1][0]), __float2half(S[2 * kk + 1][1]));
            pf[kk][3] = packhf(__float2half(S[2 * kk + 1][2]), __float2half(S[2 * kk + 1][3]));
        }

        // ---- O += P V (1-pass) ----
        const uint32_t vb = kb + OFF_VH;
        #pragma unroll
        for (int kk = 0; kk < 4; ++kk) {
            const uint32_t cb = kk * 32 + lcolb;
            #pragma unroll
            for (int half = 0; half < 2; ++half) {
                uint32_t vf[4][4];
                #pragma unroll
                for (int u = 0; u < 4; ++u)
                    ldm4(vf[u], vb + ((half * 4 + u) * 16 + lrow) * AV_STR + cb);
                #pragma unroll
                for (int u = 0; u < 4; ++u) {
                    const int np = half * 4 + u;
                    mma16816(O[2 * np],     pf[kk], vf[u][0], vf[u][2]);
                    mma16816(O[2 * np + 1], pf[kk], vf[u][1], vf[u][3]);
                }
            }
        }

        __syncthreads();
        if (c + 2 < 32)
            load_kv_chunk(sb, c & 1, c + 2, bh, k_g, v_g, tid);
        CP_ASYNC_COMMIT();
    }

    // ---- epilogue: ctx single fp16 ----
    const float inv0 = 1.0f / lr0, inv1 = 1.0f / lr1;
    const int t0 = q0 + wid * 16 + g;
    const int t1 = t0 + 8;
    #pragma unroll
    for (int nv = 0; nv < 16; ++nv) {
        const int d = h * HD + nv * 8 + 2 * t;
        const size_t o0 = ((size_t)b * TT + t0) * DD + d;
        const size_t o1 = ((size_t)b * TT + t1) * DD + d;
        *(uint32_t*)(c_g + o0) =
            packhf(__float2half(O[nv][0] * inv0), __float2half(O[nv][1] * inv0));
        *(uint32_t*)(c_g + o1) =
            packhf(__float2half(O[nv][2] * inv1), __float2half(O[nv][3] * inv1));
    }
}

// ---------------------------------------------------------------------------
extern "C" void kernel_launch(void* const* d_in, const int* in_sizes, int n_in,
                              void* d_out, int out_size)
{
    const float* hs  = (const float*)d_in[0];
    const float* enc = (const float*)d_in[1];
    const float* Wq  = (const float*)d_in[2];
    const float* Wk  = (const float*)d_in[3];
    const float* Wv  = (const float*)d_in[4];
    const float* Wo  = (const float*)d_in[5];
    const float* cq  = (const float*)d_in[6];
    const float* sq  = (const float*)d_in[7];
    const float* ck  = (const float*)d_in[8];
    const float* sk  = (const float*)d_in[9];

    __half *hs_c, *enc_c, *wq_c, *wk_c, *wv_c, *wo_c;
    __half *q_c, *k_c, *v_c, *c_c;
    cudaGetSymbolAddress((void**)&hs_c,  g_hs);
    cudaGetSymbolAddress((void**)&enc_c, g_enc);
    cudaGetSymbolAddress((void**)&wq_c,  g_wq);
    cudaGetSymbolAddress((void**)&wk_c,  g_wk);
    cudaGetSymbolAddress((void**)&wv_c,  g_wv);
    cudaGetSymbolAddress((void**)&wo_c,  g_wo);
    cudaGetSymbolAddress((void**)&q_c, g_q);
    cudaGetSymbolAddress((void**)&k_c, g_k);
    cudaGetSymbolAddress((void**)&v_c, g_v);
    cudaGetSymbolAddress((void**)&c_c, g_c);

    {
        const size_t nblocks = TOT_E / 32 / 256;   // 4096
        conv_all<<<(unsigned)nblocks, 256>>>(
            hs, enc, Wq, Wk, Wv, Wo, hs_c, enc_c, wq_c, wk_c, wv_c, wo_c);
    }

    cudaFuncSetAttribute(gemm_kernel<true>,
                         cudaFuncAttributeMaxDynamicSharedMemorySize, SMEM_GEMM);
    cudaFuncSetAttribute(gemm_kernel<false>,
                         cudaFuncAttributeMaxDynamicSharedMemorySize, SMEM_GEMM);
    cudaFuncSetAttribute(attn_kernel,
                         cudaFuncAttributeMaxDynamicSharedMemorySize, ATT_SMEM);

    // Q/K/V projections (+RoPE, +head split, +V transpose)
    gemm_kernel<true><<<dim3(DD / 128, MM / 128, 3), GTHREADS, SMEM_GEMM>>>(
        hs_c, enc_c, wq_c, wk_c, wv_c,
        cq, sq, ck, sk, q_c, k_c, v_c, nullptr);

    // Attention (BR=64, 2 CTAs/SM)
    attn_kernel<<<dim3(TT / 64, BB * HH), ATHREADS, ATT_SMEM>>>(
        q_c, k_c, v_c, c_c);

    // Output projection (fp32 out)
    gemm_kernel<false><<<dim3(DD / 128, MM / 128, 1), GTHREADS, SMEM_GEMM>>>(
        c_c, nullptr, wo_c, nullptr, nullptr,
        nullptr, nullptr, nullptr, nullptr,
        nullptr, nullptr, nullptr, (float*)d_out);
}